// round 13
// baseline (speedup 1.0000x reference)
#include <cuda_runtime.h>
#include <stdint.h>
#include <math.h>

// ---------------- problem constants ----------------
#define BSZ     256
#define NCLS    10
#define INCAPS  1152

// ---------------- scratch (device globals; no allocs allowed) ----------------
__device__ float g_h   [256 * 256 * 400];   // conv1 output (100 MB)
__device__ float g_wT  [256 * 81 * 256];    // prim weights transposed [ic][tap][oc]
__device__ float g_p   [256 * 256 * 36];    // prim conv output
__device__ float g_u   [256 * 1152 * 8];    // squashed primary capsules
__device__ float g_vecs[256 * 10 * 16];     // routed output vectors
__device__ float g_dec [256 * 160];         // masked decoder input
__device__ float g_h1  [256 * 512];
__device__ float g_h2  [256 * 1024];

// ---------------- packed f32x2 helpers (Blackwell FFMA2) ----------------
__device__ __forceinline__ unsigned long long pack2(float v) {
    unsigned long long r;
    asm("mov.b64 %0, {%1, %1};" : "=l"(r) : "f"(v));
    return r;
}
__device__ __forceinline__ void fma2(unsigned long long& d,
                                     unsigned long long a, unsigned long long b) {
    asm("fma.rn.f32x2 %0, %1, %2, %0;" : "+l"(d) : "l"(a), "l"(b));
}
__device__ __forceinline__ float2 unpack2(unsigned long long v) {
    float2 r;
    asm("mov.b64 {%0, %1}, %2;" : "=f"(r.x), "=f"(r.y) : "l"(v));
    return r;
}

// ---------------- cp.async helpers ----------------
__device__ __forceinline__ void cp_async16(unsigned int smem_addr, const void* gptr) {
    asm volatile("cp.async.cg.shared.global [%0], [%1], 16;"
                 :: "r"(smem_addr), "l"(gptr));
}
__device__ __forceinline__ void cp_commit() {
    asm volatile("cp.async.commit_group;");
}
template<int N>
__device__ __forceinline__ void cp_wait() {
    asm volatile("cp.async.wait_group %0;" :: "n"(N));
}

// ======================================================================
// conv1 + relu: per block: one image, 32 output channels. (unchanged)
// ======================================================================
__global__ __launch_bounds__(320) void conv1_kernel(
    const float* __restrict__ x, const float* __restrict__ w,
    const float* __restrict__ bias)
{
    __shared__ __align__(16) float img[784];
    __shared__ __align__(16) float ws[81 * 32];   // [tap][oc]
    int b = blockIdx.x, oc0 = blockIdx.y * 32;
    int tid = threadIdx.x;

    for (int idx = tid; idx < 784; idx += 320) img[idx] = x[b * 784 + idx];
    for (int idx = tid; idx < 32 * 81; idx += 320) {
        int oc = idx / 81, tap = idx - oc * 81;
        ws[tap * 32 + oc] = w[(oc0 + oc) * 81 + tap];
    }
    __syncthreads();

    int ocg = tid & 7;
    int pg  = tid >> 3;
    int row = pg >> 1;
    int c0  = (pg & 1) * 10;

    unsigned long long acc2[10][2];
#pragma unroll
    for (int p = 0; p < 10; p++) { acc2[p][0] = 0ull; acc2[p][1] = 0ull; }

#pragma unroll 1
    for (int ky = 0; ky < 9; ky++) {
        const float* r = img + (row + ky) * 28 + c0;
        unsigned long long xv2[18];
#pragma unroll
        for (int j = 0; j < 18; j++) xv2[j] = pack2(r[j]);
#pragma unroll
        for (int kx = 0; kx < 9; kx++) {
            ulonglong2 wv = *(const ulonglong2*)(ws + (ky * 9 + kx) * 32 + ocg * 4);
#pragma unroll
            for (int p = 0; p < 10; p++) {
                fma2(acc2[p][0], xv2[p + kx], wv.x);
                fma2(acc2[p][1], xv2[p + kx], wv.y);
            }
        }
    }
    int ocb = oc0 + ocg * 4;
    float bv[4] = { bias[ocb], bias[ocb + 1], bias[ocb + 2], bias[ocb + 3] };
#pragma unroll
    for (int p = 0; p < 10; p++) {
        float2 a0 = unpack2(acc2[p][0]);
        float2 a1 = unpack2(acc2[p][1]);
        float vals[4] = { a0.x + bv[0], a0.y + bv[1], a1.x + bv[2], a1.y + bv[3] };
#pragma unroll
        for (int c = 0; c < 4; c++) {
            float v = vals[c];
            g_h[(b * 256 + ocb + c) * 400 + row * 20 + c0 + p] = v > 0.f ? v : 0.f;
        }
    }
}

// ======================================================================
// prim weight transpose: w[oc][ic][tap] -> wT[ic][tap][oc]
// ======================================================================
__global__ void transpose_w_kernel(const float* __restrict__ w)
{
    int idx = blockIdx.x * 256 + threadIdx.x;
    if (idx >= 256 * 256 * 81) return;
    int oc  = idx / (256 * 81);
    int r   = idx - oc * (256 * 81);
    int ic  = r / 81;
    int tap = r - ic * 81;
    g_wT[(ic * 81 + tap) * 256 + oc] = w[idx];
}

// dummy no-op: keeps prim in the ncu capture slot (-s 5 -c 1)
__global__ void dummy_kernel() {}

// ======================================================================
// prim conv (9x9, stride 2, 256->256ch, out 6x6) + bias
// TWO IMAGES PER BLOCK: one weight fill serves 2 images -> fill/barrier/ALU
// overhead per FLOP halves. Double-buffered cp.async as before.
// grid (128 img-pairs, 4 oc-quarters) = 512 blocks = ONE WAVE @ 4 blk/SM.
// 96 thr (6 oy x 16 ocg of 4 oc); smem 47.9KB; regs capped for 4 blk/SM.
// ======================================================================
__global__ __launch_bounds__(96, 4) void prim_kernel(const float* __restrict__ bias)
{
    __shared__ __align__(16) float img[2][2][400];   // [buf][img][plane]
    __shared__ __align__(16) float ws[2][81 * 64];   // [buf][tap][oc]
    int b0 = blockIdx.x * 2, oc0 = blockIdx.y * 64;
    int tid = threadIdx.x;
    int ocg = tid & 15, oy = tid >> 4;   // oy 0..5

    const float* hsrc = g_h + (size_t)b0 * 102400;   // img1 at +102400
    const float* wsrc = g_wT + oc0;                  // + ic*20736 + tap*256

    unsigned int s_img[2], s_ws[2];
    s_img[0] = (unsigned int)__cvta_generic_to_shared(&img[0][0][0]);
    s_img[1] = (unsigned int)__cvta_generic_to_shared(&img[1][0][0]);
    s_ws[0]  = (unsigned int)__cvta_generic_to_shared(&ws[0][0]);
    s_ws[1]  = (unsigned int)__cvta_generic_to_shared(&ws[1][0]);

    // ---- prologue: prefetch ic = 0 into buffer 0 ----
    {
        // 2 images x 100 float4
        for (int idx = tid; idx < 200; idx += 96) {
            int im = (idx >= 100);
            int q  = idx - im * 100;
            cp_async16(s_img[0] + im * 1600 + q * 16, hsrc + im * 102400 + q * 4);
        }
        for (int idx = tid; idx < 81 * 16; idx += 96) {
            int tap = idx >> 4, q = idx & 15;
            cp_async16(s_ws[0] + (tap * 64 + q * 4) * 4, wsrc + tap * 256 + q * 4);
        }
        cp_commit();
    }

    unsigned long long acc2[2][6][2];
#pragma unroll
    for (int im = 0; im < 2; im++)
#pragma unroll
        for (int p = 0; p < 6; p++) { acc2[im][p][0] = 0ull; acc2[im][p][1] = 0ull; }

#pragma unroll 1
    for (int ic = 0; ic < 256; ic++) {
        int cur = ic & 1, nxt = cur ^ 1;
        __syncthreads();   // A: compute on buf[nxt] (prev iter) finished everywhere

        if (ic + 1 < 256) {
            const float* hs = hsrc + (ic + 1) * 400;
            for (int idx = tid; idx < 200; idx += 96) {
                int im = (idx >= 100);
                int q  = idx - im * 100;
                cp_async16(s_img[nxt] + im * 1600 + q * 16, hs + im * 102400 + q * 4);
            }
            const float* wn = wsrc + (ic + 1) * 20736;
            for (int idx = tid; idx < 81 * 16; idx += 96) {
                int tap = idx >> 4, q = idx & 15;
                cp_async16(s_ws[nxt] + (tap * 64 + q * 4) * 4, wn + tap * 256 + q * 4);
            }
            cp_commit();
            cp_wait<1>();   // buf[cur] group complete for this thread
        } else {
            cp_wait<0>();
        }
        __syncthreads();   // B: buf[cur] visible to all

        const float* wc = ws[cur];
#pragma unroll 1
        for (int ky = 0; ky < 9; ky++) {
            const float* wk = wc + ky * (9 * 64) + ocg * 4;
#pragma unroll
            for (int im = 0; im < 2; im++) {
                const float4* rp = (const float4*)(&img[cur][im][0] + oy * 40 + ky * 20);
                float4 f0 = rp[0], f1 = rp[1], f2 = rp[2], f3 = rp[3], f4 = rp[4];
                unsigned long long xv2[19];
                xv2[0]  = pack2(f0.x); xv2[1]  = pack2(f0.y); xv2[2]  = pack2(f0.z); xv2[3]  = pack2(f0.w);
                xv2[4]  = pack2(f1.x); xv2[5]  = pack2(f1.y); xv2[6]  = pack2(f1.z); xv2[7]  = pack2(f1.w);
                xv2[8]  = pack2(f2.x); xv2[9]  = pack2(f2.y); xv2[10] = pack2(f2.z); xv2[11] = pack2(f2.w);
                xv2[12] = pack2(f3.x); xv2[13] = pack2(f3.y); xv2[14] = pack2(f3.z); xv2[15] = pack2(f3.w);
                xv2[16] = pack2(f4.x); xv2[17] = pack2(f4.y); xv2[18] = pack2(f4.z);
#pragma unroll
                for (int kx = 0; kx < 9; kx++) {
                    ulonglong2 wv = *(const ulonglong2*)(wk + kx * 64);
#pragma unroll
                    for (int p = 0; p < 6; p++) {
                        fma2(acc2[im][p][0], xv2[2 * p + kx], wv.x);
                        fma2(acc2[im][p][1], xv2[2 * p + kx], wv.y);
                    }
                }
            }
        }
    }

    int ocb = oc0 + ocg * 4;
    float bv[4] = { bias[ocb], bias[ocb + 1], bias[ocb + 2], bias[ocb + 3] };
#pragma unroll
    for (int im = 0; im < 2; im++) {
#pragma unroll
        for (int p = 0; p < 6; p++) {
            float2 a0 = unpack2(acc2[im][p][0]);
            float2 a1 = unpack2(acc2[im][p][1]);
            float vals[4] = { a0.x + bv[0], a0.y + bv[1], a1.x + bv[2], a1.y + bv[3] };
#pragma unroll
            for (int c = 0; c < 4; c++)
                g_p[((b0 + im) * 256 + ocb + c) * 36 + oy * 6 + p] = vals[c];
        }
    }
}

// ======================================================================
// primary capsule squash: p[b, d*32+m, s] -> u[b, i=m*36+s, d]
// ======================================================================
__global__ void squash_kernel()
{
    int idx = blockIdx.x * 256 + threadIdx.x;
    if (idx >= 256 * 1152) return;
    int b = idx / 1152;
    int i = idx - b * 1152;
    int m = i / 36;
    int s = i - m * 36;
    const float* src = g_p + (b * 256 + m) * 36 + s;
    float v[8]; float sq = 0.f;
#pragma unroll
    for (int d = 0; d < 8; d++) { float t = src[d * 1152]; v[d] = t; sq += t * t; }
    float coef = (sq / (1.f + sq)) * rsqrtf(sq);
    float* dst = g_u + (size_t)idx * 8;
#pragma unroll
    for (int d = 0; d < 8; d++) dst[d] = v[d] * coef;
}

// ======================================================================
// fused routing-by-agreement: one block per (class o, batch b).
// ======================================================================
__device__ __forceinline__ float warpSum(float v) {
#pragma unroll
    for (int o = 16; o; o >>= 1) v += __shfl_xor_sync(0xffffffffu, v, o);
    return v;
}
__device__ __forceinline__ float warpMax(float v) {
#pragma unroll
    for (int o = 16; o; o >>= 1) v = fmaxf(v, __shfl_xor_sync(0xffffffffu, v, o));
    return v;
}

#define ROUTE_SMEM_FLOATS (18432 + 1152 + 160)

__global__ __launch_bounds__(256) void routing_kernel(const float* __restrict__ rw)
{
    extern __shared__ float sm[];
    float* P      = sm;
    float* logits = sm + 18432;
    float* red    = sm + 19584;

    int o = blockIdx.x, b = blockIdx.y;
    int tid = threadIdx.x;
    int lane = tid & 31, wid = tid >> 5;

    float sacc[16];
#pragma unroll
    for (int j = 0; j < 16; j++) sacc[j] = 0.f;

    for (int i = tid; i < 1152; i += 256) {
        const float4* up = (const float4*)(g_u + ((size_t)b * 1152 + i) * 8);
        float4 ua = up[0], ub = up[1];
        float uu[8] = { ua.x, ua.y, ua.z, ua.w, ub.x, ub.y, ub.z, ub.w };
        const float4* wr = (const float4*)(rw + (size_t)(o * 1152 + i) * 128);
        float pj[16];
#pragma unroll
        for (int j = 0; j < 16; j++) pj[j] = 0.f;
#pragma unroll
        for (int d = 0; d < 8; d++) {
            float ud = uu[d];
            float4 w0 = wr[d*4+0], w1 = wr[d*4+1], w2 = wr[d*4+2], w3 = wr[d*4+3];
            pj[0]+=ud*w0.x; pj[1]+=ud*w0.y; pj[2]+=ud*w0.z; pj[3]+=ud*w0.w;
            pj[4]+=ud*w1.x; pj[5]+=ud*w1.y; pj[6]+=ud*w1.z; pj[7]+=ud*w1.w;
            pj[8]+=ud*w2.x; pj[9]+=ud*w2.y; pj[10]+=ud*w2.z; pj[11]+=ud*w2.w;
            pj[12]+=ud*w3.x; pj[13]+=ud*w3.y; pj[14]+=ud*w3.z; pj[15]+=ud*w3.w;
        }
        float4* Pd = (float4*)(P + i * 16);
        Pd[0] = make_float4(pj[0], pj[1], pj[2], pj[3]);
        Pd[1] = make_float4(pj[4], pj[5], pj[6], pj[7]);
        Pd[2] = make_float4(pj[8], pj[9], pj[10], pj[11]);
        Pd[3] = make_float4(pj[12], pj[13], pj[14], pj[15]);
#pragma unroll
        for (int j = 0; j < 16; j++) sacc[j] += pj[j];
    }

    __syncthreads();
#pragma unroll
    for (int j = 0; j < 16; j++) sacc[j] = warpSum(sacc[j]);
    if (lane == 0) {
#pragma unroll
        for (int j = 0; j < 16; j++) red[16 + wid * 16 + j] = sacc[j];
    }
    __syncthreads();
    if (tid < 16) {
        float t = 0.f;
#pragma unroll
        for (int w2 = 0; w2 < 8; w2++) t += red[16 + w2 * 16 + tid];
        red[144 + tid] = t;
    }
    __syncthreads();

    float v[16];
    {
        float sq = 0.f;
#pragma unroll
        for (int j = 0; j < 16; j++) { float s = red[144 + j] * (1.f / 1152.f); v[j] = s; sq += s * s; }
        float coef = (sq / (1.f + sq)) * rsqrtf(sq);
#pragma unroll
        for (int j = 0; j < 16; j++) v[j] *= coef;
    }
    __syncthreads();

    for (int i = tid; i < 1152; i += 256) {
        const float4* Pd = (const float4*)(P + i * 16);
        float4 p0 = Pd[0], p1 = Pd[1], p2 = Pd[2], p3 = Pd[3];
        logits[i] = p0.x*v[0]+p0.y*v[1]+p0.z*v[2]+p0.w*v[3]
                  + p1.x*v[4]+p1.y*v[5]+p1.z*v[6]+p1.w*v[7]
                  + p2.x*v[8]+p2.y*v[9]+p2.z*v[10]+p2.w*v[11]
                  + p3.x*v[12]+p3.y*v[13]+p3.z*v[14]+p3.w*v[15];
    }
    __syncthreads();

    for (int t = 0; t < 2; t++) {
        float lm = -1e30f;
        for (int i = tid; i < 1152; i += 256) lm = fmaxf(lm, logits[i]);
        lm = warpMax(lm);
        if (lane == 0) red[wid] = lm;
        __syncthreads();
        float M = red[0];
#pragma unroll
        for (int w2 = 1; w2 < 8; w2++) M = fmaxf(M, red[w2]);
        __syncthreads();

        float zp = 0.f;
        float sp[16];
#pragma unroll
        for (int j = 0; j < 16; j++) sp[j] = 0.f;
        for (int i = tid; i < 1152; i += 256) {
            float e = expf(logits[i] - M);
            zp += e;
            const float4* Pd = (const float4*)(P + i * 16);
            float4 p0 = Pd[0], p1 = Pd[1], p2 = Pd[2], p3 = Pd[3];
            sp[0]+=e*p0.x; sp[1]+=e*p0.y; sp[2]+=e*p0.z; sp[3]+=e*p0.w;
            sp[4]+=e*p1.x; sp[5]+=e*p1.y; sp[6]+=e*p1.z; sp[7]+=e*p1.w;
            sp[8]+=e*p2.x; sp[9]+=e*p2.y; sp[10]+=e*p2.z; sp[11]+=e*p2.w;
            sp[12]+=e*p3.x; sp[13]+=e*p3.y; sp[14]+=e*p3.z; sp[15]+=e*p3.w;
        }
        zp = warpSum(zp);
#pragma unroll
        for (int j = 0; j < 16; j++) sp[j] = warpSum(sp[j]);
        if (lane == 0) {
            red[wid] = zp;
#pragma unroll
            for (int j = 0; j < 16; j++) red[16 + wid * 16 + j] = sp[j];
        }
        __syncthreads();
        float Z = 0.f;
#pragma unroll
        for (int w2 = 0; w2 < 8; w2++) Z += red[w2];
        float sq = 0.f;
#pragma unroll
        for (int j = 0; j < 16; j++) {
            float t2 = 0.f;
#pragma unroll
            for (int w2 = 0; w2 < 8; w2++) t2 += red[16 + w2 * 16 + j];
            float s = t2 / Z;
            v[j] = s; sq += s * s;
        }
        float coef = (sq / (1.f + sq)) * rsqrtf(sq);
#pragma unroll
        for (int j = 0; j < 16; j++) v[j] *= coef;
        __syncthreads();

        if (t == 0) {
            for (int i = tid; i < 1152; i += 256) {
                const float4* Pd = (const float4*)(P + i * 16);
                float4 p0 = Pd[0], p1 = Pd[1], p2 = Pd[2], p3 = Pd[3];
                float dot = p0.x*v[0]+p0.y*v[1]+p0.z*v[2]+p0.w*v[3]
                          + p1.x*v[4]+p1.y*v[5]+p1.z*v[6]+p1.w*v[7]
                          + p2.x*v[8]+p2.y*v[9]+p2.z*v[10]+p2.w*v[11]
                          + p3.x*v[12]+p3.y*v[13]+p3.z*v[14]+p3.w*v[15];
                logits[i] += dot;
            }
            __syncthreads();
        }
    }

    if (tid < 16) g_vecs[(b * 10 + o) * 16 + tid] = v[tid];
}

// ======================================================================
// class norms -> softmax -> d_out[0..2560); argmax one-hot mask -> g_dec
// ======================================================================
__global__ void mask_kernel(float* __restrict__ cls_out)
{
    int b = blockIdx.x;
    int lane = threadIdx.x;
    float nrm = -1e30f;
    if (lane < 10) {
        float sq = 0.f;
        const float* vp = g_vecs + (b * 10 + lane) * 16;
#pragma unroll
        for (int j = 0; j < 16; j++) { float t = vp[j]; sq += t * t; }
        nrm = sqrtf(sq);
    }
    float m = nrm;
#pragma unroll
    for (int off = 16; off; off >>= 1) m = fmaxf(m, __shfl_xor_sync(0xffffffffu, m, off));
    float e = (lane < 10) ? expf(nrm - m) : 0.f;
    float Z = e;
#pragma unroll
    for (int off = 16; off; off >>= 1) Z += __shfl_xor_sync(0xffffffffu, Z, off);
    if (lane < 10) cls_out[b * 10 + lane] = e / Z;

    float bv = nrm; int bi = (lane < 10) ? lane : 1000;
#pragma unroll
    for (int off = 16; off; off >>= 1) {
        float ov = __shfl_xor_sync(0xffffffffu, bv, off);
        int   oi = __shfl_xor_sync(0xffffffffu, bi, off);
        if (ov > bv || (ov == bv && oi < bi)) { bv = ov; bi = oi; }
    }
#pragma unroll
    for (int r2 = 0; r2 < 5; r2++) {
        int k = lane + 32 * r2;
        int oo = k >> 4, j = k & 15;
        g_dec[b * 160 + k] = (oo == bi) ? g_vecs[(b * 10 + oo) * 16 + j] : 0.f;
    }
}

// ======================================================================
// generic SGEMM C = act(A[M,K] @ B[K,N] + bias), 64x64 tile, 256 threads
// ======================================================================
template<int ACT>
__global__ __launch_bounds__(256) void gemm_bias_act(
    const float* __restrict__ A, const float* __restrict__ Bm,
    const float* __restrict__ bias, float* __restrict__ C,
    int M, int N, int K)
{
    __shared__ __align__(16) float As[16][64];
    __shared__ __align__(16) float Bs[16][64];
    int tid = threadIdx.x;
    int bn = blockIdx.x * 64, bm = blockIdx.y * 64;
    int tx = tid & 15, ty = tid >> 4;
    int ar = tid >> 2, ac = (tid & 3) * 4;
    int br = tid >> 4, bc = (tid & 15) * 4;

    unsigned long long acc2[4][2];
#pragma unroll
    for (int i = 0; i < 4; i++) { acc2[i][0] = 0ull; acc2[i][1] = 0ull; }

    for (int k0 = 0; k0 < K; k0 += 16) {
        float4 av = *(const float4*)(A + (size_t)(bm + ar) * K + k0 + ac);
        As[ac + 0][ar] = av.x; As[ac + 1][ar] = av.y;
        As[ac + 2][ar] = av.z; As[ac + 3][ar] = av.w;
        float4 bvv;
        int bcol = bn + bc;
        if (bcol + 3 < N) {
            bvv = *(const float4*)(Bm + (size_t)(k0 + br) * N + bcol);
        } else {
            bvv.x = (bcol + 0 < N) ? Bm[(size_t)(k0 + br) * N + bcol + 0] : 0.f;
            bvv.y = (bcol + 1 < N) ? Bm[(size_t)(k0 + br) * N + bcol + 1] : 0.f;
            bvv.z = (bcol + 2 < N) ? Bm[(size_t)(k0 + br) * N + bcol + 2] : 0.f;
            bvv.w = (bcol + 3 < N) ? Bm[(size_t)(k0 + br) * N + bcol + 3] : 0.f;
        }
        *(float4*)(&Bs[br][bc]) = bvv;
        __syncthreads();
#pragma unroll
        for (int kk = 0; kk < 16; kk++) {
            float4 a = *(const float4*)(&As[kk][ty * 4]);
            ulonglong2 bq = *(const ulonglong2*)(&Bs[kk][tx * 4]);
            unsigned long long a2[4] = { pack2(a.x), pack2(a.y), pack2(a.z), pack2(a.w) };
#pragma unroll
            for (int i = 0; i < 4; i++) {
                fma2(acc2[i][0], a2[i], bq.x);
                fma2(acc2[i][1], a2[i], bq.y);
            }
        }
        __syncthreads();
    }
#pragma unroll
    for (int i = 0; i < 4; i++) {
        int mrow = bm + ty * 4 + i;
        float2 a0 = unpack2(acc2[i][0]);
        float2 a1 = unpack2(acc2[i][1]);
        float vals[4] = { a0.x, a0.y, a1.x, a1.y };
#pragma unroll
        for (int j = 0; j < 4; j++) {
            int ncol = bn + tx * 4 + j;
            if (ncol < N) {
                float vv = vals[j] + bias[ncol];
                if (ACT == 0) vv = vv > 0.f ? vv : 0.f;
                else          vv = 1.f / (1.f + expf(-vv));
                C[(size_t)mrow * N + ncol] = vv;
            }
        }
    }
}

// ======================================================================
extern "C" void kernel_launch(void* const* d_in, const int* in_sizes, int n_in,
                              void* d_out, int out_size)
{
    const float* x   = (const float*)d_in[0];
    const float* c1w = (const float*)d_in[1];
    const float* c1b = (const float*)d_in[2];
    const float* pw  = (const float*)d_in[3];
    const float* pb  = (const float*)d_in[4];
    const float* rw  = (const float*)d_in[5];
    const float* w1  = (const float*)d_in[6];
    const float* b1  = (const float*)d_in[7];
    const float* w2  = (const float*)d_in[8];
    const float* b2  = (const float*)d_in[9];
    const float* w3  = (const float*)d_in[10];
    const float* b3  = (const float*)d_in[11];
    float* out = (float*)d_out;

    cudaFuncSetAttribute(routing_kernel, cudaFuncAttributeMaxDynamicSharedMemorySize,
                         ROUTE_SMEM_FLOATS * 4);

    conv1_kernel<<<dim3(256, 8), 320>>>(x, c1w, c1b);
    transpose_w_kernel<<<(256 * 256 * 81 + 255) / 256, 256>>>(pw);
    dummy_kernel<<<1, 32>>>();   // keeps prim in the fixed ncu capture slot
    prim_kernel<<<dim3(128, 4), 96>>>(pb);
    squash_kernel<<<(256 * 1152 + 255) / 256, 256>>>();
    routing_kernel<<<dim3(10, 256), 256, ROUTE_SMEM_FLOATS * 4>>>(rw);
    mask_kernel<<<256, 32>>>(out);
    gemm_bias_act<0><<<dim3(8, 4), 256>>>(g_dec, w1, b1, g_h1, 256, 512, 160);
    gemm_bias_act<0><<<dim3(16, 4), 256>>>(g_h1, w2, b2, g_h2, 256, 1024, 512);
    gemm_bias_act<1><<<dim3(13, 4), 256>>>(g_h2, w3, b3, out + 2560, 256, 784, 1024);
}

// round 15
// speedup vs baseline: 1.6012x; 1.6012x over previous
#include <cuda_runtime.h>
#include <cuda_bf16.h>
#include <stdint.h>
#include <math.h>

// ---------------- problem constants ----------------
#define BSZ     256
#define NCLS    10
#define INCAPS  1152

// ---------------- scratch (device globals; no allocs allowed) ----------------
__device__ float g_h   [256 * 256 * 400];   // conv1 output (fp32, NCHW)
__device__ __nv_bfloat16 g_hh [256 * 400 * 256];  // h hi, NHWC: [(b*400+p)*256+ic]
__device__ __nv_bfloat16 g_hl [256 * 400 * 256];  // h lo
__device__ __nv_bfloat16 g_wh2[81 * 256 * 256];   // w hi: [(tap*256+oc)*256+ic]
__device__ __nv_bfloat16 g_wl2[81 * 256 * 256];   // w lo
__device__ float g_p   [256 * 256 * 36];    // prim conv output
__device__ float g_u   [256 * 1152 * 8];    // squashed primary capsules
__device__ float g_vecs[256 * 10 * 16];     // routed output vectors
__device__ float g_dec [256 * 160];         // masked decoder input
__device__ float g_h1  [256 * 512];
__device__ float g_h2  [256 * 1024];

// ---------------- packed f32x2 helpers (Blackwell FFMA2) ----------------
__device__ __forceinline__ unsigned long long pack2(float v) {
    unsigned long long r;
    asm("mov.b64 %0, {%1, %1};" : "=l"(r) : "f"(v));
    return r;
}
__device__ __forceinline__ void fma2(unsigned long long& d,
                                     unsigned long long a, unsigned long long b) {
    asm("fma.rn.f32x2 %0, %1, %2, %0;" : "+l"(d) : "l"(a), "l"(b));
}
__device__ __forceinline__ float2 unpack2(unsigned long long v) {
    float2 r;
    asm("mov.b64 {%0, %1}, %2;" : "=f"(r.x), "=f"(r.y) : "l"(v));
    return r;
}

// ---------------- cp.async helpers ----------------
__device__ __forceinline__ void cp_async16(unsigned int smem_addr, const void* gptr) {
    asm volatile("cp.async.cg.shared.global [%0], [%1], 16;"
                 :: "r"(smem_addr), "l"(gptr));
}
__device__ __forceinline__ void cp_commit() {
    asm volatile("cp.async.commit_group;");
}
template<int N>
__device__ __forceinline__ void cp_wait() {
    asm volatile("cp.async.wait_group %0;" :: "n"(N));
}

// ---------------- warp MMA helpers (base PTX, works on sm_103 non-'a') ----
__device__ __forceinline__ void ldsm_x4(unsigned& r0, unsigned& r1,
                                        unsigned& r2, unsigned& r3, unsigned addr) {
    asm volatile("ldmatrix.sync.aligned.m8n8.x4.shared.b16 {%0,%1,%2,%3}, [%4];"
                 : "=r"(r0), "=r"(r1), "=r"(r2), "=r"(r3) : "r"(addr));
}
__device__ __forceinline__ void mma16816(float* c, const unsigned* a, const unsigned* b) {
    asm volatile(
        "mma.sync.aligned.m16n8k16.row.col.f32.bf16.bf16.f32 "
        "{%0,%1,%2,%3}, {%4,%5,%6,%7}, {%8,%9}, {%0,%1,%2,%3};"
        : "+f"(c[0]), "+f"(c[1]), "+f"(c[2]), "+f"(c[3])
        : "r"(a[0]), "r"(a[1]), "r"(a[2]), "r"(a[3]), "r"(b[0]), "r"(b[1]));
}

// ======================================================================
// conv1 + relu (unchanged, FFMA2)
// ======================================================================
__global__ __launch_bounds__(320) void conv1_kernel(
    const float* __restrict__ x, const float* __restrict__ w,
    const float* __restrict__ bias)
{
    __shared__ __align__(16) float img[784];
    __shared__ __align__(16) float ws[81 * 32];
    int b = blockIdx.x, oc0 = blockIdx.y * 32;
    int tid = threadIdx.x;

    for (int idx = tid; idx < 784; idx += 320) img[idx] = x[b * 784 + idx];
    for (int idx = tid; idx < 32 * 81; idx += 320) {
        int oc = idx / 81, tap = idx - oc * 81;
        ws[tap * 32 + oc] = w[(oc0 + oc) * 81 + tap];
    }
    __syncthreads();

    int ocg = tid & 7;
    int pg  = tid >> 3;
    int row = pg >> 1;
    int c0  = (pg & 1) * 10;

    unsigned long long acc2[10][2];
#pragma unroll
    for (int p = 0; p < 10; p++) { acc2[p][0] = 0ull; acc2[p][1] = 0ull; }

#pragma unroll 1
    for (int ky = 0; ky < 9; ky++) {
        const float* r = img + (row + ky) * 28 + c0;
        unsigned long long xv2[18];
#pragma unroll
        for (int j = 0; j < 18; j++) xv2[j] = pack2(r[j]);
#pragma unroll
        for (int kx = 0; kx < 9; kx++) {
            ulonglong2 wv = *(const ulonglong2*)(ws + (ky * 9 + kx) * 32 + ocg * 4);
#pragma unroll
            for (int p = 0; p < 10; p++) {
                fma2(acc2[p][0], xv2[p + kx], wv.x);
                fma2(acc2[p][1], xv2[p + kx], wv.y);
            }
        }
    }
    int ocb = oc0 + ocg * 4;
    float bv[4] = { bias[ocb], bias[ocb + 1], bias[ocb + 2], bias[ocb + 3] };
#pragma unroll
    for (int p = 0; p < 10; p++) {
        float2 a0 = unpack2(acc2[p][0]);
        float2 a1 = unpack2(acc2[p][1]);
        float vals[4] = { a0.x + bv[0], a0.y + bv[1], a1.x + bv[2], a1.y + bv[3] };
#pragma unroll
        for (int c = 0; c < 4; c++) {
            float v = vals[c];
            g_h[(b * 256 + ocb + c) * 400 + row * 20 + c0 + p] = v > 0.f ? v : 0.f;
        }
    }
}

// ======================================================================
// wsplit: pw[oc][ic][tap] -> g_wh2/g_wl2 [(tap*256+oc)*256+ic] (bf16 hi/lo)
// ======================================================================
__global__ void wsplit_kernel(const float* __restrict__ w)
{
    int idx = blockIdx.x * 256 + threadIdx.x;
    if (idx >= 81 * 256 * 256) return;
    int ic  = idx & 255;
    int r   = idx >> 8;
    int oc  = r & 255;
    int tap = r >> 8;
    float v = w[(oc * 256 + ic) * 81 + tap];
    __nv_bfloat16 hi = __float2bfloat16(v);
    g_wh2[idx] = hi;
    g_wl2[idx] = __float2bfloat16(v - __bfloat162float(hi));
}

// ======================================================================
// hsplit: g_h [b][ic][p] -> g_hh/g_hl [(b*400+p)*256+ic] (bf16 hi/lo)
// ======================================================================
__global__ void hsplit_kernel()
{
    __shared__ float t[32][33];
    int b  = blockIdx.z;
    int p0 = blockIdx.x * 32, ic0 = blockIdx.y * 32;
    int tx = threadIdx.x, ty = threadIdx.y;   // 32 x 8

    for (int i = ty; i < 32; i += 8) {
        int p = p0 + tx;
        t[i][tx] = (p < 400) ? g_h[((size_t)b * 256 + ic0 + i) * 400 + p] : 0.f;
    }
    __syncthreads();
    for (int i = ty; i < 32; i += 8) {
        int p = p0 + i;
        if (p < 400) {
            float v = t[tx][i];
            __nv_bfloat16 hi = __float2bfloat16(v);
            float lo = v - __bfloat162float(hi);
            size_t o = ((size_t)b * 400 + p) * 256 + ic0 + tx;
            g_hh[o] = hi;
            g_hl[o] = __float2bfloat16(lo);
        }
    }
}

// ======================================================================
// prim conv as warp-MMA bf16 implicit GEMM (tap-decomposed, 2-term split)
// C[pos 128][oc 128] per block; 8 warps, warp tile 64(pos) x 32(oc).
// K: 81 taps x 4 ic-chunks of 64; per chunk 3 passes (Ah*Bh, Al*Bh, Ah*Bl)
// into the same fp32 accumulators. Double-buffered cp.async (128KB smem).
// grid (72 pos-blocks, 2 oc-blocks) = 144 blocks = one wave.
// ======================================================================
#define TILE_B   16384                // one 128x64 bf16 tile
#define BUF_B    (4 * TILE_B)         // Ah, Al, Bh, Bl
#define PRIM_SMEM (2 * BUF_B)         // 128 KB

__global__ __launch_bounds__(256, 1) void prim_mma_kernel(const float* __restrict__ bias)
{
    extern __shared__ __align__(128) char smem[];
    unsigned sbase = (unsigned)__cvta_generic_to_shared(smem);
    int tid = threadIdx.x, warp = tid >> 5, lane = tid & 31;
    int nblk = blockIdx.x;              // position blocks (M)
    int mpos0 = nblk * 128;
    int oc0 = blockIdx.y * 128;

    int wm = (warp >> 2) * 64;          // warp pos offset within tile
    int wn = (warp & 3) * 32;           // warp oc offset within tile

    // ---- fill indexing: each thread fills 4 chunks of one row in 4 arrays
    int frow = tid & 127, fhalf = tid >> 7;
    int pg = mpos0 + frow;
    int fb = pg / 36, fr = pg - fb * 36;
    int foy = fr / 6, fox = fr - foy * 6;
    size_t abase = ((size_t)fb * 400 + foy * 40 + fox * 2) * 256;  // + (ky*20+kx)*256 + ic0
    size_t wbase = (size_t)(oc0 + frow) * 256;                     // + tap*65536 + ic0
    unsigned drow = frow * 128;
    int swz = frow & 7;

    float acc[4][4][4];
#pragma unroll
    for (int mi = 0; mi < 4; mi++)
#pragma unroll
        for (int ni = 0; ni < 4; ni++)
#pragma unroll
            for (int k = 0; k < 4; k++) acc[mi][ni][k] = 0.f;

    // ---- prologue: fill buffer 0 with (tap 0, chunk 0)
    {
        const __nv_bfloat16* sAh = g_hh + abase;
        const __nv_bfloat16* sAl = g_hl + abase;
        const __nv_bfloat16* sBh = g_wh2 + wbase;
        const __nv_bfloat16* sBl = g_wl2 + wbase;
#pragma unroll
        for (int j0 = 0; j0 < 4; j0++) {
            int j = fhalf * 4 + j0;
            unsigned so = drow + (unsigned)((j ^ swz) * 16);
            cp_async16(sbase + so,              sAh + j * 8);
            cp_async16(sbase + TILE_B + so,     sAl + j * 8);
            cp_async16(sbase + 2 * TILE_B + so, sBh + j * 8);
            cp_async16(sbase + 3 * TILE_B + so, sBl + j * 8);
        }
        cp_commit();
    }

#pragma unroll 1
    for (int it = 0; it < 324; it++) {
        int cur = it & 1, nxt = cur ^ 1;
        __syncthreads();   // everyone done computing from buf[nxt]

        if (it + 1 < 324) {
            int tap = (it + 1) >> 2, ck = (it + 1) & 3;
            int ky = tap / 9, kx = tap - ky * 9;
            const __nv_bfloat16* sAh = g_hh + abase + (ky * 20 + kx) * 256 + ck * 64;
            const __nv_bfloat16* sAl = g_hl + abase + (ky * 20 + kx) * 256 + ck * 64;
            const __nv_bfloat16* sBh = g_wh2 + wbase + (size_t)tap * 65536 + ck * 64;
            const __nv_bfloat16* sBl = g_wl2 + wbase + (size_t)tap * 65536 + ck * 64;
            unsigned dst = sbase + nxt * BUF_B;
#pragma unroll
            for (int j0 = 0; j0 < 4; j0++) {
                int j = fhalf * 4 + j0;
                unsigned so = drow + (unsigned)((j ^ swz) * 16);
                cp_async16(dst + so,              sAh + j * 8);
                cp_async16(dst + TILE_B + so,     sAl + j * 8);
                cp_async16(dst + 2 * TILE_B + so, sBh + j * 8);
                cp_async16(dst + 3 * TILE_B + so, sBl + j * 8);
            }
            cp_commit();
            cp_wait<1>();
        } else {
            cp_wait<0>();
        }
        __syncthreads();   // buf[cur] visible

        unsigned bufb = sbase + cur * BUF_B;
        // 3 passes: (Ah,Bh), (Al,Bh), (Ah,Bl)
        const unsigned aoffs[3] = { 0u, TILE_B, 0u };
        const unsigned boffs[3] = { 2u * TILE_B, 2u * TILE_B, 3u * TILE_B };
#pragma unroll 1
        for (int pr = 0; pr < 3; pr++) {
            unsigned aBuf = bufb + aoffs[pr];
            unsigned bBuf = bufb + boffs[pr];
#pragma unroll
            for (int ks = 0; ks < 4; ks++) {
                unsigned a[4][4], bfr[4][2];
#pragma unroll
                for (int mi = 0; mi < 4; mi++) {
                    int row = wm + mi * 16 + (lane & 15);
                    int chunk = ks * 2 + (lane >> 4);
                    unsigned addr = aBuf + row * 128 + ((chunk ^ (row & 7)) * 16);
                    ldsm_x4(a[mi][0], a[mi][1], a[mi][2], a[mi][3], addr);
                }
#pragma unroll
                for (int nj = 0; nj < 2; nj++) {
                    int row = wn + nj * 16 + ((lane >> 4) << 3) + (lane & 7);
                    int chunk = ks * 2 + ((lane >> 3) & 1);
                    unsigned addr = bBuf + row * 128 + ((chunk ^ (row & 7)) * 16);
                    ldsm_x4(bfr[nj * 2][0], bfr[nj * 2][1],
                            bfr[nj * 2 + 1][0], bfr[nj * 2 + 1][1], addr);
                }
#pragma unroll
                for (int mi = 0; mi < 4; mi++)
#pragma unroll
                    for (int ni = 0; ni < 4; ni++)
                        mma16816(acc[mi][ni], a[mi], bfr[ni]);
            }
        }
    }

    // ---- epilogue: acc -> g_p with bias
    int g = lane >> 2, tg = lane & 3;
#pragma unroll
    for (int mi = 0; mi < 4; mi++) {
        int pos0 = mpos0 + wm + mi * 16 + g;
        int pos1 = pos0 + 8;
        int b0 = pos0 / 36, pp0 = pos0 - b0 * 36;
        int b1 = pos1 / 36, pp1 = pos1 - b1 * 36;
#pragma unroll
        for (int ni = 0; ni < 4; ni++) {
            int oc = oc0 + wn + ni * 8 + tg * 2;
            float bv0 = bias[oc], bv1 = bias[oc + 1];
            g_p[((size_t)b0 * 256 + oc)     * 36 + pp0] = acc[mi][ni][0] + bv0;
            g_p[((size_t)b0 * 256 + oc + 1) * 36 + pp0] = acc[mi][ni][1] + bv1;
            g_p[((size_t)b1 * 256 + oc)     * 36 + pp1] = acc[mi][ni][2] + bv0;
            g_p[((size_t)b1 * 256 + oc + 1) * 36 + pp1] = acc[mi][ni][3] + bv1;
        }
    }
}

// ======================================================================
// primary capsule squash (unchanged)
// ======================================================================
__global__ void squash_kernel()
{
    int idx = blockIdx.x * 256 + threadIdx.x;
    if (idx >= 256 * 1152) return;
    int b = idx / 1152;
    int i = idx - b * 1152;
    int m = i / 36;
    int s = i - m * 36;
    const float* src = g_p + (b * 256 + m) * 36 + s;
    float v[8]; float sq = 0.f;
#pragma unroll
    for (int d = 0; d < 8; d++) { float t = src[d * 1152]; v[d] = t; sq += t * t; }
    float coef = (sq / (1.f + sq)) * rsqrtf(sq);
    float* dst = g_u + (size_t)idx * 8;
#pragma unroll
    for (int d = 0; d < 8; d++) dst[d] = v[d] * coef;
}

// ======================================================================
// fused routing-by-agreement (unchanged)
// ======================================================================
__device__ __forceinline__ float warpSum(float v) {
#pragma unroll
    for (int o = 16; o; o >>= 1) v += __shfl_xor_sync(0xffffffffu, v, o);
    return v;
}
__device__ __forceinline__ float warpMax(float v) {
#pragma unroll
    for (int o = 16; o; o >>= 1) v = fmaxf(v, __shfl_xor_sync(0xffffffffu, v, o));
    return v;
}

#define ROUTE_SMEM_FLOATS (18432 + 1152 + 160)

__global__ __launch_bounds__(256) void routing_kernel(const float* __restrict__ rw)
{
    extern __shared__ float sm[];
    float* P      = sm;
    float* logits = sm + 18432;
    float* red    = sm + 19584;

    int o = blockIdx.x, b = blockIdx.y;
    int tid = threadIdx.x;
    int lane = tid & 31, wid = tid >> 5;

    float sacc[16];
#pragma unroll
    for (int j = 0; j < 16; j++) sacc[j] = 0.f;

    for (int i = tid; i < 1152; i += 256) {
        const float4* up = (const float4*)(g_u + ((size_t)b * 1152 + i) * 8);
        float4 ua = up[0], ub = up[1];
        float uu[8] = { ua.x, ua.y, ua.z, ua.w, ub.x, ub.y, ub.z, ub.w };
        const float4* wr = (const float4*)(rw + (size_t)(o * 1152 + i) * 128);
        float pj[16];
#pragma unroll
        for (int j = 0; j < 16; j++) pj[j] = 0.f;
#pragma unroll
        for (int d = 0; d < 8; d++) {
            float ud = uu[d];
            float4 w0 = wr[d*4+0], w1 = wr[d*4+1], w2 = wr[d*4+2], w3 = wr[d*4+3];
            pj[0]+=ud*w0.x; pj[1]+=ud*w0.y; pj[2]+=ud*w0.z; pj[3]+=ud*w0.w;
            pj[4]+=ud*w1.x; pj[5]+=ud*w1.y; pj[6]+=ud*w1.z; pj[7]+=ud*w1.w;
            pj[8]+=ud*w2.x; pj[9]+=ud*w2.y; pj[10]+=ud*w2.z; pj[11]+=ud*w2.w;
            pj[12]+=ud*w3.x; pj[13]+=ud*w3.y; pj[14]+=ud*w3.z; pj[15]+=ud*w3.w;
        }
        float4* Pd = (float4*)(P + i * 16);
        Pd[0] = make_float4(pj[0], pj[1], pj[2], pj[3]);
        Pd[1] = make_float4(pj[4], pj[5], pj[6], pj[7]);
        Pd[2] = make_float4(pj[8], pj[9], pj[10], pj[11]);
        Pd[3] = make_float4(pj[12], pj[13], pj[14], pj[15]);
#pragma unroll
        for (int j = 0; j < 16; j++) sacc[j] += pj[j];
    }

    __syncthreads();
#pragma unroll
    for (int j = 0; j < 16; j++) sacc[j] = warpSum(sacc[j]);
    if (lane == 0) {
#pragma unroll
        for (int j = 0; j < 16; j++) red[16 + wid * 16 + j] = sacc[j];
    }
    __syncthreads();
    if (tid < 16) {
        float t = 0.f;
#pragma unroll
        for (int w2 = 0; w2 < 8; w2++) t += red[16 + w2 * 16 + tid];
        red[144 + tid] = t;
    }
    __syncthreads();

    float v[16];
    {
        float sq = 0.f;
#pragma unroll
        for (int j = 0; j < 16; j++) { float s = red[144 + j] * (1.f / 1152.f); v[j] = s; sq += s * s; }
        float coef = (sq / (1.f + sq)) * rsqrtf(sq);
#pragma unroll
        for (int j = 0; j < 16; j++) v[j] *= coef;
    }
    __syncthreads();

    for (int i = tid; i < 1152; i += 256) {
        const float4* Pd = (const float4*)(P + i * 16);
        float4 p0 = Pd[0], p1 = Pd[1], p2 = Pd[2], p3 = Pd[3];
        logits[i] = p0.x*v[0]+p0.y*v[1]+p0.z*v[2]+p0.w*v[3]
                  + p1.x*v[4]+p1.y*v[5]+p1.z*v[6]+p1.w*v[7]
                  + p2.x*v[8]+p2.y*v[9]+p2.z*v[10]+p2.w*v[11]
                  + p3.x*v[12]+p3.y*v[13]+p3.z*v[14]+p3.w*v[15];
    }
    __syncthreads();

    for (int t = 0; t < 2; t++) {
        float lm = -1e30f;
        for (int i = tid; i < 1152; i += 256) lm = fmaxf(lm, logits[i]);
        lm = warpMax(lm);
        if (lane == 0) red[wid] = lm;
        __syncthreads();
        float M = red[0];
#pragma unroll
        for (int w2 = 1; w2 < 8; w2++) M = fmaxf(M, red[w2]);
        __syncthreads();

        float zp = 0.f;
        float sp[16];
#pragma unroll
        for (int j = 0; j < 16; j++) sp[j] = 0.f;
        for (int i = tid; i < 1152; i += 256) {
            float e = expf(logits[i] - M);
            zp += e;
            const float4* Pd = (const float4*)(P + i * 16);
            float4 p0 = Pd[0], p1 = Pd[1], p2 = Pd[2], p3 = Pd[3];
            sp[0]+=e*p0.x; sp[1]+=e*p0.y; sp[2]+=e*p0.z; sp[3]+=e*p0.w;
            sp[4]+=e*p1.x; sp[5]+=e*p1.y; sp[6]+=e*p1.z; sp[7]+=e*p1.w;
            sp[8]+=e*p2.x; sp[9]+=e*p2.y; sp[10]+=e*p2.z; sp[11]+=e*p2.w;
            sp[12]+=e*p3.x; sp[13]+=e*p3.y; sp[14]+=e*p3.z; sp[15]+=e*p3.w;
        }
        zp = warpSum(zp);
#pragma unroll
        for (int j = 0; j < 16; j++) sp[j] = warpSum(sp[j]);
        if (lane == 0) {
            red[wid] = zp;
#pragma unroll
            for (int j = 0; j < 16; j++) red[16 + wid * 16 + j] = sp[j];
        }
        __syncthreads();
        float Z = 0.f;
#pragma unroll
        for (int w2 = 0; w2 < 8; w2++) Z += red[w2];
        float sq = 0.f;
#pragma unroll
        for (int j = 0; j < 16; j++) {
            float t2 = 0.f;
#pragma unroll
            for (int w2 = 0; w2 < 8; w2++) t2 += red[16 + w2 * 16 + j];
            float s = t2 / Z;
            v[j] = s; sq += s * s;
        }
        float coef = (sq / (1.f + sq)) * rsqrtf(sq);
#pragma unroll
        for (int j = 0; j < 16; j++) v[j] *= coef;
        __syncthreads();

        if (t == 0) {
            for (int i = tid; i < 1152; i += 256) {
                const float4* Pd = (const float4*)(P + i * 16);
                float4 p0 = Pd[0], p1 = Pd[1], p2 = Pd[2], p3 = Pd[3];
                float dot = p0.x*v[0]+p0.y*v[1]+p0.z*v[2]+p0.w*v[3]
                          + p1.x*v[4]+p1.y*v[5]+p1.z*v[6]+p1.w*v[7]
                          + p2.x*v[8]+p2.y*v[9]+p2.z*v[10]+p2.w*v[11]
                          + p3.x*v[12]+p3.y*v[13]+p3.z*v[14]+p3.w*v[15];
                logits[i] += dot;
            }
            __syncthreads();
        }
    }

    if (tid < 16) g_vecs[(b * 10 + o) * 16 + tid] = v[tid];
}

// ======================================================================
// class norms -> softmax -> d_out[0..2560); argmax one-hot mask -> g_dec
// ======================================================================
__global__ void mask_kernel(float* __restrict__ cls_out)
{
    int b = blockIdx.x;
    int lane = threadIdx.x;
    float nrm = -1e30f;
    if (lane < 10) {
        float sq = 0.f;
        const float* vp = g_vecs + (b * 10 + lane) * 16;
#pragma unroll
        for (int j = 0; j < 16; j++) { float t = vp[j]; sq += t * t; }
        nrm = sqrtf(sq);
    }
    float m = nrm;
#pragma unroll
    for (int off = 16; off; off >>= 1) m = fmaxf(m, __shfl_xor_sync(0xffffffffu, m, off));
    float e = (lane < 10) ? expf(nrm - m) : 0.f;
    float Z = e;
#pragma unroll
    for (int off = 16; off; off >>= 1) Z += __shfl_xor_sync(0xffffffffu, Z, off);
    if (lane < 10) cls_out[b * 10 + lane] = e / Z;

    float bv = nrm; int bi = (lane < 10) ? lane : 1000;
#pragma unroll
    for (int off = 16; off; off >>= 1) {
        float ov = __shfl_xor_sync(0xffffffffu, bv, off);
        int   oi = __shfl_xor_sync(0xffffffffu, bi, off);
        if (ov > bv || (ov == bv && oi < bi)) { bv = ov; bi = oi; }
    }
#pragma unroll
    for (int r2 = 0; r2 < 5; r2++) {
        int k = lane + 32 * r2;
        int oo = k >> 4, j = k & 15;
        g_dec[b * 160 + k] = (oo == bi) ? g_vecs[(b * 10 + oo) * 16 + j] : 0.f;
    }
}

// ======================================================================
// generic SGEMM C = act(A[M,K] @ B[K,N] + bias), 64x64 tile (unchanged)
// ======================================================================
template<int ACT>
__global__ __launch_bounds__(256) void gemm_bias_act(
    const float* __restrict__ A, const float* __restrict__ Bm,
    const float* __restrict__ bias, float* __restrict__ C,
    int M, int N, int K)
{
    __shared__ __align__(16) float As[16][64];
    __shared__ __align__(16) float Bs[16][64];
    int tid = threadIdx.x;
    int bn = blockIdx.x * 64, bm = blockIdx.y * 64;
    int tx = tid & 15, ty = tid >> 4;
    int ar = tid >> 2, ac = (tid & 3) * 4;
    int br = tid >> 4, bc = (tid & 15) * 4;

    unsigned long long acc2[4][2];
#pragma unroll
    for (int i = 0; i < 4; i++) { acc2[i][0] = 0ull; acc2[i][1] = 0ull; }

    for (int k0 = 0; k0 < K; k0 += 16) {
        float4 av = *(const float4*)(A + (size_t)(bm + ar) * K + k0 + ac);
        As[ac + 0][ar] = av.x; As[ac + 1][ar] = av.y;
        As[ac + 2][ar] = av.z; As[ac + 3][ar] = av.w;
        float4 bvv;
        int bcol = bn + bc;
        if (bcol + 3 < N) {
            bvv = *(const float4*)(Bm + (size_t)(k0 + br) * N + bcol);
        } else {
            bvv.x = (bcol + 0 < N) ? Bm[(size_t)(k0 + br) * N + bcol + 0] : 0.f;
            bvv.y = (bcol + 1 < N) ? Bm[(size_t)(k0 + br) * N + bcol + 1] : 0.f;
            bvv.z = (bcol + 2 < N) ? Bm[(size_t)(k0 + br) * N + bcol + 2] : 0.f;
            bvv.w = (bcol + 3 < N) ? Bm[(size_t)(k0 + br) * N + bcol + 3] : 0.f;
        }
        *(float4*)(&Bs[br][bc]) = bvv;
        __syncthreads();
#pragma unroll
        for (int kk = 0; kk < 16; kk++) {
            float4 a = *(const float4*)(&As[kk][ty * 4]);
            ulonglong2 bq = *(const ulonglong2*)(&Bs[kk][tx * 4]);
            unsigned long long a2[4] = { pack2(a.x), pack2(a.y), pack2(a.z), pack2(a.w) };
#pragma unroll
            for (int i = 0; i < 4; i++) {
                fma2(acc2[i][0], a2[i], bq.x);
                fma2(acc2[i][1], a2[i], bq.y);
            }
        }
        __syncthreads();
    }
#pragma unroll
    for (int i = 0; i < 4; i++) {
        int mrow = bm + ty * 4 + i;
        float2 a0 = unpack2(acc2[i][0]);
        float2 a1 = unpack2(acc2[i][1]);
        float vals[4] = { a0.x, a0.y, a1.x, a1.y };
#pragma unroll
        for (int j = 0; j < 4; j++) {
            int ncol = bn + tx * 4 + j;
            if (ncol < N) {
                float vv = vals[j] + bias[ncol];
                if (ACT == 0) vv = vv > 0.f ? vv : 0.f;
                else          vv = 1.f / (1.f + expf(-vv));
                C[(size_t)mrow * N + ncol] = vv;
            }
        }
    }
}

// ======================================================================
extern "C" void kernel_launch(void* const* d_in, const int* in_sizes, int n_in,
                              void* d_out, int out_size)
{
    const float* x   = (const float*)d_in[0];
    const float* c1w = (const float*)d_in[1];
    const float* c1b = (const float*)d_in[2];
    const float* pw  = (const float*)d_in[3];
    const float* pb  = (const float*)d_in[4];
    const float* rw  = (const float*)d_in[5];
    const float* w1  = (const float*)d_in[6];
    const float* b1  = (const float*)d_in[7];
    const float* w2  = (const float*)d_in[8];
    const float* b2  = (const float*)d_in[9];
    const float* w3  = (const float*)d_in[10];
    const float* b3  = (const float*)d_in[11];
    float* out = (float*)d_out;

    cudaFuncSetAttribute(routing_kernel, cudaFuncAttributeMaxDynamicSharedMemorySize,
                         ROUTE_SMEM_FLOATS * 4);
    cudaFuncSetAttribute(prim_mma_kernel, cudaFuncAttributeMaxDynamicSharedMemorySize,
                         PRIM_SMEM);

    conv1_kernel<<<dim3(256, 8), 320>>>(x, c1w, c1b);
    wsplit_kernel<<<(81 * 256 * 256 + 255) / 256, 256>>>(pw);
    hsplit_kernel<<<dim3(13, 8, 256), dim3(32, 8)>>>();
    prim_mma_kernel<<<dim3(72, 2), 256, PRIM_SMEM>>>(pb);   // profiled slot
    squash_kernel<<<(256 * 1152 + 255) / 256, 256>>>();
    routing_kernel<<<dim3(10, 256), 256, ROUTE_SMEM_FLOATS * 4>>>(rw);
    mask_kernel<<<256, 32>>>(out);
    gemm_bias_act<0><<<dim3(8, 4), 256>>>(g_dec, w1, b1, g_h1, 256, 512, 160);
    gemm_bias_act<0><<<dim3(16, 4), 256>>>(g_h1, w2, b2, g_h2, 256, 1024, 512);
    gemm_bias_act<1><<<dim3(13, 4), 256>>>(g_h2, w3, b3, out + 2560, 256, 784, 1024);
}

// round 16
// speedup vs baseline: 1.6022x; 1.0006x over previous
#include <cuda_runtime.h>
#include <cuda_bf16.h>
#include <stdint.h>
#include <math.h>

// ---------------- problem constants ----------------
#define BSZ     256
#define NCLS    10
#define INCAPS  1152

// ---------------- scratch (device globals; no allocs allowed) ----------------
__device__ float g_h   [256 * 256 * 400];   // conv1 output (fp32, NCHW)
__device__ __nv_bfloat16 g_hh [256 * 400 * 256];  // h hi, NHWC: [(b*400+p)*256+ic]
__device__ __nv_bfloat16 g_hl [256 * 400 * 256];  // h lo
__device__ __nv_bfloat16 g_wh2[81 * 256 * 256];   // w hi: [(tap*256+oc)*256+ic]
__device__ __nv_bfloat16 g_wl2[81 * 256 * 256];   // w lo
__device__ float g_p   [256 * 256 * 36];    // prim conv output
__device__ float g_u   [256 * 1152 * 8];    // squashed primary capsules
__device__ float g_vecs[256 * 10 * 16];     // routed output vectors
__device__ float g_dec [256 * 160];         // masked decoder input
__device__ float g_h1  [256 * 512];
__device__ float g_h2  [256 * 1024];

// ---------------- packed f32x2 helpers (Blackwell FFMA2) ----------------
__device__ __forceinline__ unsigned long long pack2(float v) {
    unsigned long long r;
    asm("mov.b64 %0, {%1, %1};" : "=l"(r) : "f"(v));
    return r;
}
__device__ __forceinline__ void fma2(unsigned long long& d,
                                     unsigned long long a, unsigned long long b) {
    asm("fma.rn.f32x2 %0, %1, %2, %0;" : "+l"(d) : "l"(a), "l"(b));
}
__device__ __forceinline__ float2 unpack2(unsigned long long v) {
    float2 r;
    asm("mov.b64 {%0, %1}, %2;" : "=f"(r.x), "=f"(r.y) : "l"(v));
    return r;
}

// ---------------- cp.async helpers ----------------
__device__ __forceinline__ void cp_async16(unsigned int smem_addr, const void* gptr) {
    asm volatile("cp.async.cg.shared.global [%0], [%1], 16;"
                 :: "r"(smem_addr), "l"(gptr));
}
__device__ __forceinline__ void cp_commit() {
    asm volatile("cp.async.commit_group;");
}
template<int N>
__device__ __forceinline__ void cp_wait() {
    asm volatile("cp.async.wait_group %0;" :: "n"(N));
}

// ---------------- warp MMA helpers (base PTX, works on sm_103 non-'a') ----
__device__ __forceinline__ void ldsm_x4(unsigned& r0, unsigned& r1,
                                        unsigned& r2, unsigned& r3, unsigned addr) {
    asm volatile("ldmatrix.sync.aligned.m8n8.x4.shared.b16 {%0,%1,%2,%3}, [%4];"
                 : "=r"(r0), "=r"(r1), "=r"(r2), "=r"(r3) : "r"(addr));
}
__device__ __forceinline__ void mma16816(float* c, const unsigned* a, const unsigned* b) {
    asm volatile(
        "mma.sync.aligned.m16n8k16.row.col.f32.bf16.bf16.f32 "
        "{%0,%1,%2,%3}, {%4,%5,%6,%7}, {%8,%9}, {%0,%1,%2,%3};"
        : "+f"(c[0]), "+f"(c[1]), "+f"(c[2]), "+f"(c[3])
        : "r"(a[0]), "r"(a[1]), "r"(a[2]), "r"(a[3]), "r"(b[0]), "r"(b[1]));
}

// ======================================================================
// conv1 + relu (unchanged, FFMA2)
// ======================================================================
__global__ __launch_bounds__(320) void conv1_kernel(
    const float* __restrict__ x, const float* __restrict__ w,
    const float* __restrict__ bias)
{
    __shared__ __align__(16) float img[784];
    __shared__ __align__(16) float ws[81 * 32];
    int b = blockIdx.x, oc0 = blockIdx.y * 32;
    int tid = threadIdx.x;

    for (int idx = tid; idx < 784; idx += 320) img[idx] = x[b * 784 + idx];
    for (int idx = tid; idx < 32 * 81; idx += 320) {
        int oc = idx / 81, tap = idx - oc * 81;
        ws[tap * 32 + oc] = w[(oc0 + oc) * 81 + tap];
    }
    __syncthreads();

    int ocg = tid & 7;
    int pg  = tid >> 3;
    int row = pg >> 1;
    int c0  = (pg & 1) * 10;

    unsigned long long acc2[10][2];
#pragma unroll
    for (int p = 0; p < 10; p++) { acc2[p][0] = 0ull; acc2[p][1] = 0ull; }

#pragma unroll 1
    for (int ky = 0; ky < 9; ky++) {
        const float* r = img + (row + ky) * 28 + c0;
        unsigned long long xv2[18];
#pragma unroll
        for (int j = 0; j < 18; j++) xv2[j] = pack2(r[j]);
#pragma unroll
        for (int kx = 0; kx < 9; kx++) {
            ulonglong2 wv = *(const ulonglong2*)(ws + (ky * 9 + kx) * 32 + ocg * 4);
#pragma unroll
            for (int p = 0; p < 10; p++) {
                fma2(acc2[p][0], xv2[p + kx], wv.x);
                fma2(acc2[p][1], xv2[p + kx], wv.y);
            }
        }
    }
    int ocb = oc0 + ocg * 4;
    float bv[4] = { bias[ocb], bias[ocb + 1], bias[ocb + 2], bias[ocb + 3] };
#pragma unroll
    for (int p = 0; p < 10; p++) {
        float2 a0 = unpack2(acc2[p][0]);
        float2 a1 = unpack2(acc2[p][1]);
        float vals[4] = { a0.x + bv[0], a0.y + bv[1], a1.x + bv[2], a1.y + bv[3] };
#pragma unroll
        for (int c = 0; c < 4; c++) {
            float v = vals[c];
            g_h[(b * 256 + ocb + c) * 400 + row * 20 + c0 + p] = v > 0.f ? v : 0.f;
        }
    }
}

// ======================================================================
// wsplit: pw[oc][ic][tap] -> g_wh2/g_wl2 [(tap*256+oc)*256+ic] (bf16 hi/lo)
// ======================================================================
__global__ void wsplit_kernel(const float* __restrict__ w)
{
    int idx = blockIdx.x * 256 + threadIdx.x;
    if (idx >= 81 * 256 * 256) return;
    int ic  = idx & 255;
    int r   = idx >> 8;
    int oc  = r & 255;
    int tap = r >> 8;
    float v = w[(oc * 256 + ic) * 81 + tap];
    __nv_bfloat16 hi = __float2bfloat16(v);
    g_wh2[idx] = hi;
    g_wl2[idx] = __float2bfloat16(v - __bfloat162float(hi));
}

// ======================================================================
// hsplit: g_h [b][ic][p] -> g_hh/g_hl [(b*400+p)*256+ic] (bf16 hi/lo)
// ======================================================================
__global__ void hsplit_kernel()
{
    __shared__ float t[32][33];
    int b  = blockIdx.z;
    int p0 = blockIdx.x * 32, ic0 = blockIdx.y * 32;
    int tx = threadIdx.x, ty = threadIdx.y;   // 32 x 8

    for (int i = ty; i < 32; i += 8) {
        int p = p0 + tx;
        t[i][tx] = (p < 400) ? g_h[((size_t)b * 256 + ic0 + i) * 400 + p] : 0.f;
    }
    __syncthreads();
    for (int i = ty; i < 32; i += 8) {
        int p = p0 + i;
        if (p < 400) {
            float v = t[tx][i];
            __nv_bfloat16 hi = __float2bfloat16(v);
            float lo = v - __bfloat162float(hi);
            size_t o = ((size_t)b * 400 + p) * 256 + ic0 + tx;
            g_hh[o] = hi;
            g_hl[o] = __float2bfloat16(lo);
        }
    }
}

// ======================================================================
// prim conv as warp-MMA bf16 implicit GEMM (tap-decomposed, 2-term split)
// C[pos 128][oc 128] per block; 16 warps (4x4), warp tile 32(pos) x 32(oc).
// Per k-step: load Ah/Al/Bh/Bl fragments ONCE, run 3 MMA passes from regs.
// Double-buffered cp.async (128KB smem). grid 72x2 = 144 blocks = one wave.
// ======================================================================
#define TILE_B   16384                // one 128x64 bf16 tile
#define BUF_B    (4 * TILE_B)         // Ah, Al, Bh, Bl
#define PRIM_SMEM (2 * BUF_B)         // 128 KB

__global__ __launch_bounds__(512, 1) void prim_mma_kernel(const float* __restrict__ bias)
{
    extern __shared__ __align__(128) char smem[];
    unsigned sbase = (unsigned)__cvta_generic_to_shared(smem);
    int tid = threadIdx.x, warp = tid >> 5, lane = tid & 31;
    int mpos0 = blockIdx.x * 128;
    int oc0 = blockIdx.y * 128;

    int wm = (warp >> 2) * 32;          // warp pos offset within tile
    int wn = (warp & 3) * 32;           // warp oc offset within tile

    // ---- fill indexing: 512 threads; each fills 2 of 8 j-chunks of one row x 4 arrays
    int frow = tid & 127, fq = tid >> 7;   // fq 0..3
    int pg = mpos0 + frow;
    int fb = pg / 36, fr = pg - fb * 36;
    int foy = fr / 6, fox = fr - foy * 6;
    size_t abase = ((size_t)fb * 400 + foy * 40 + fox * 2) * 256;  // + (ky*20+kx)*256 + ic0
    size_t wbase = (size_t)(oc0 + frow) * 256;                     // + tap*65536 + ic0
    unsigned drow = frow * 128;
    int swz = frow & 7;

    float acc[2][4][4];
#pragma unroll
    for (int mi = 0; mi < 2; mi++)
#pragma unroll
        for (int ni = 0; ni < 4; ni++)
#pragma unroll
            for (int k = 0; k < 4; k++) acc[mi][ni][k] = 0.f;

    // ---- prologue: fill buffer 0 with (tap 0, chunk 0)
    {
        const __nv_bfloat16* sAh = g_hh + abase;
        const __nv_bfloat16* sAl = g_hl + abase;
        const __nv_bfloat16* sBh = g_wh2 + wbase;
        const __nv_bfloat16* sBl = g_wl2 + wbase;
#pragma unroll
        for (int j0 = 0; j0 < 2; j0++) {
            int j = fq * 2 + j0;
            unsigned so = drow + (unsigned)((j ^ swz) * 16);
            cp_async16(sbase + so,              sAh + j * 8);
            cp_async16(sbase + TILE_B + so,     sAl + j * 8);
            cp_async16(sbase + 2 * TILE_B + so, sBh + j * 8);
            cp_async16(sbase + 3 * TILE_B + so, sBl + j * 8);
        }
        cp_commit();
    }

#pragma unroll 1
    for (int it = 0; it < 324; it++) {
        int cur = it & 1, nxt = cur ^ 1;
        __syncthreads();   // everyone done computing from buf[nxt]

        if (it + 1 < 324) {
            int tap = (it + 1) >> 2, ck = (it + 1) & 3;
            int ky = tap / 9, kx = tap - ky * 9;
            const __nv_bfloat16* sAh = g_hh + abase + (ky * 20 + kx) * 256 + ck * 64;
            const __nv_bfloat16* sAl = g_hl + abase + (ky * 20 + kx) * 256 + ck * 64;
            const __nv_bfloat16* sBh = g_wh2 + wbase + (size_t)tap * 65536 + ck * 64;
            const __nv_bfloat16* sBl = g_wl2 + wbase + (size_t)tap * 65536 + ck * 64;
            unsigned dst = sbase + nxt * BUF_B;
#pragma unroll
            for (int j0 = 0; j0 < 2; j0++) {
                int j = fq * 2 + j0;
                unsigned so = drow + (unsigned)((j ^ swz) * 16);
                cp_async16(dst + so,              sAh + j * 8);
                cp_async16(dst + TILE_B + so,     sAl + j * 8);
                cp_async16(dst + 2 * TILE_B + so, sBh + j * 8);
                cp_async16(dst + 3 * TILE_B + so, sBl + j * 8);
            }
            cp_commit();
            cp_wait<1>();
        } else {
            cp_wait<0>();
        }
        __syncthreads();   // buf[cur] visible

        unsigned bufb = sbase + cur * BUF_B;
#pragma unroll
        for (int ks = 0; ks < 4; ks++) {
            unsigned ah[2][4], al[2][4], bh[4][2], bl[4][2];
            // A fragments (hi + lo), 2 row-tiles of 16
#pragma unroll
            for (int mi = 0; mi < 2; mi++) {
                int row = wm + mi * 16 + (lane & 15);
                int chunk = ks * 2 + (lane >> 4);
                unsigned addr = bufb + row * 128 + ((chunk ^ (row & 7)) * 16);
                ldsm_x4(ah[mi][0], ah[mi][1], ah[mi][2], ah[mi][3], addr);
                ldsm_x4(al[mi][0], al[mi][1], al[mi][2], al[mi][3], addr + TILE_B);
            }
            // B fragments (hi + lo), 2 ldsm each covering 16 oc
#pragma unroll
            for (int nj = 0; nj < 2; nj++) {
                int row = wn + nj * 16 + ((lane >> 4) << 3) + (lane & 7);
                int chunk = ks * 2 + ((lane >> 3) & 1);
                unsigned addr = bufb + 2 * TILE_B + row * 128 + ((chunk ^ (row & 7)) * 16);
                ldsm_x4(bh[nj * 2][0], bh[nj * 2][1],
                        bh[nj * 2 + 1][0], bh[nj * 2 + 1][1], addr);
                ldsm_x4(bl[nj * 2][0], bl[nj * 2][1],
                        bl[nj * 2 + 1][0], bl[nj * 2 + 1][1], addr + TILE_B);
            }
            // 3 passes from registers
#pragma unroll
            for (int mi = 0; mi < 2; mi++)
#pragma unroll
                for (int ni = 0; ni < 4; ni++) {
                    mma16816(acc[mi][ni], ah[mi], bh[ni]);
                    mma16816(acc[mi][ni], al[mi], bh[ni]);
                    mma16816(acc[mi][ni], ah[mi], bl[ni]);
                }
        }
    }

    // ---- epilogue: acc -> g_p with bias
    int g = lane >> 2, tg = lane & 3;
#pragma unroll
    for (int mi = 0; mi < 2; mi++) {
        int pos0 = mpos0 + wm + mi * 16 + g;
        int pos1 = pos0 + 8;
        int b0 = pos0 / 36, pp0 = pos0 - b0 * 36;
        int b1 = pos1 / 36, pp1 = pos1 - b1 * 36;
#pragma unroll
        for (int ni = 0; ni < 4; ni++) {
            int oc = oc0 + wn + ni * 8 + tg * 2;
            float bv0 = bias[oc], bv1 = bias[oc + 1];
            g_p[((size_t)b0 * 256 + oc)     * 36 + pp0] = acc[mi][ni][0] + bv0;
            g_p[((size_t)b0 * 256 + oc + 1) * 36 + pp0] = acc[mi][ni][1] + bv1;
            g_p[((size_t)b1 * 256 + oc)     * 36 + pp1] = acc[mi][ni][2] + bv0;
            g_p[((size_t)b1 * 256 + oc + 1) * 36 + pp1] = acc[mi][ni][3] + bv1;
        }
    }
}

// ======================================================================
// primary capsule squash (unchanged)
// ======================================================================
__global__ void squash_kernel()
{
    int idx = blockIdx.x * 256 + threadIdx.x;
    if (idx >= 256 * 1152) return;
    int b = idx / 1152;
    int i = idx - b * 1152;
    int m = i / 36;
    int s = i - m * 36;
    const float* src = g_p + (b * 256 + m) * 36 + s;
    float v[8]; float sq = 0.f;
#pragma unroll
    for (int d = 0; d < 8; d++) { float t = src[d * 1152]; v[d] = t; sq += t * t; }
    float coef = (sq / (1.f + sq)) * rsqrtf(sq);
    float* dst = g_u + (size_t)idx * 8;
#pragma unroll
    for (int d = 0; d < 8; d++) dst[d] = v[d] * coef;
}

// ======================================================================
// fused routing-by-agreement (unchanged)
// ======================================================================
__device__ __forceinline__ float warpSum(float v) {
#pragma unroll
    for (int o = 16; o; o >>= 1) v += __shfl_xor_sync(0xffffffffu, v, o);
    return v;
}
__device__ __forceinline__ float warpMax(float v) {
#pragma unroll
    for (int o = 16; o; o >>= 1) v = fmaxf(v, __shfl_xor_sync(0xffffffffu, v, o));
    return v;
}

#define ROUTE_SMEM_FLOATS (18432 + 1152 + 160)

__global__ __launch_bounds__(256) void routing_kernel(const float* __restrict__ rw)
{
    extern __shared__ float sm[];
    float* P      = sm;
    float* logits = sm + 18432;
    float* red    = sm + 19584;

    int o = blockIdx.x, b = blockIdx.y;
    int tid = threadIdx.x;
    int lane = tid & 31, wid = tid >> 5;

    float sacc[16];
#pragma unroll
    for (int j = 0; j < 16; j++) sacc[j] = 0.f;

    for (int i = tid; i < 1152; i += 256) {
        const float4* up = (const float4*)(g_u + ((size_t)b * 1152 + i) * 8);
        float4 ua = up[0], ub = up[1];
        float uu[8] = { ua.x, ua.y, ua.z, ua.w, ub.x, ub.y, ub.z, ub.w };
        const float4* wr = (const float4*)(rw + (size_t)(o * 1152 + i) * 128);
        float pj[16];
#pragma unroll
        for (int j = 0; j < 16; j++) pj[j] = 0.f;
#pragma unroll
        for (int d = 0; d < 8; d++) {
            float ud = uu[d];
            float4 w0 = wr[d*4+0], w1 = wr[d*4+1], w2 = wr[d*4+2], w3 = wr[d*4+3];
            pj[0]+=ud*w0.x; pj[1]+=ud*w0.y; pj[2]+=ud*w0.z; pj[3]+=ud*w0.w;
            pj[4]+=ud*w1.x; pj[5]+=ud*w1.y; pj[6]+=ud*w1.z; pj[7]+=ud*w1.w;
            pj[8]+=ud*w2.x; pj[9]+=ud*w2.y; pj[10]+=ud*w2.z; pj[11]+=ud*w2.w;
            pj[12]+=ud*w3.x; pj[13]+=ud*w3.y; pj[14]+=ud*w3.z; pj[15]+=ud*w3.w;
        }
        float4* Pd = (float4*)(P + i * 16);
        Pd[0] = make_float4(pj[0], pj[1], pj[2], pj[3]);
        Pd[1] = make_float4(pj[4], pj[5], pj[6], pj[7]);
        Pd[2] = make_float4(pj[8], pj[9], pj[10], pj[11]);
        Pd[3] = make_float4(pj[12], pj[13], pj[14], pj[15]);
#pragma unroll
        for (int j = 0; j < 16; j++) sacc[j] += pj[j];
    }

    __syncthreads();
#pragma unroll
    for (int j = 0; j < 16; j++) sacc[j] = warpSum(sacc[j]);
    if (lane == 0) {
#pragma unroll
        for (int j = 0; j < 16; j++) red[16 + wid * 16 + j] = sacc[j];
    }
    __syncthreads();
    if (tid < 16) {
        float t = 0.f;
#pragma unroll
        for (int w2 = 0; w2 < 8; w2++) t += red[16 + w2 * 16 + tid];
        red[144 + tid] = t;
    }
    __syncthreads();

    float v[16];
    {
        float sq = 0.f;
#pragma unroll
        for (int j = 0; j < 16; j++) { float s = red[144 + j] * (1.f / 1152.f); v[j] = s; sq += s * s; }
        float coef = (sq / (1.f + sq)) * rsqrtf(sq);
#pragma unroll
        for (int j = 0; j < 16; j++) v[j] *= coef;
    }
    __syncthreads();

    for (int i = tid; i < 1152; i += 256) {
        const float4* Pd = (const float4*)(P + i * 16);
        float4 p0 = Pd[0], p1 = Pd[1], p2 = Pd[2], p3 = Pd[3];
        logits[i] = p0.x*v[0]+p0.y*v[1]+p0.z*v[2]+p0.w*v[3]
                  + p1.x*v[4]+p1.y*v[5]+p1.z*v[6]+p1.w*v[7]
                  + p2.x*v[8]+p2.y*v[9]+p2.z*v[10]+p2.w*v[11]
                  + p3.x*v[12]+p3.y*v[13]+p3.z*v[14]+p3.w*v[15];
    }
    __syncthreads();

    for (int t = 0; t < 2; t++) {
        float lm = -1e30f;
        for (int i = tid; i < 1152; i += 256) lm = fmaxf(lm, logits[i]);
        lm = warpMax(lm);
        if (lane == 0) red[wid] = lm;
        __syncthreads();
        float M = red[0];
#pragma unroll
        for (int w2 = 1; w2 < 8; w2++) M = fmaxf(M, red[w2]);
        __syncthreads();

        float zp = 0.f;
        float sp[16];
#pragma unroll
        for (int j = 0; j < 16; j++) sp[j] = 0.f;
        for (int i = tid; i < 1152; i += 256) {
            float e = expf(logits[i] - M);
            zp += e;
            const float4* Pd = (const float4*)(P + i * 16);
            float4 p0 = Pd[0], p1 = Pd[1], p2 = Pd[2], p3 = Pd[3];
            sp[0]+=e*p0.x; sp[1]+=e*p0.y; sp[2]+=e*p0.z; sp[3]+=e*p0.w;
            sp[4]+=e*p1.x; sp[5]+=e*p1.y; sp[6]+=e*p1.z; sp[7]+=e*p1.w;
            sp[8]+=e*p2.x; sp[9]+=e*p2.y; sp[10]+=e*p2.z; sp[11]+=e*p2.w;
            sp[12]+=e*p3.x; sp[13]+=e*p3.y; sp[14]+=e*p3.z; sp[15]+=e*p3.w;
        }
        zp = warpSum(zp);
#pragma unroll
        for (int j = 0; j < 16; j++) sp[j] = warpSum(sp[j]);
        if (lane == 0) {
            red[wid] = zp;
#pragma unroll
            for (int j = 0; j < 16; j++) red[16 + wid * 16 + j] = sp[j];
        }
        __syncthreads();
        float Z = 0.f;
#pragma unroll
        for (int w2 = 0; w2 < 8; w2++) Z += red[w2];
        float sq = 0.f;
#pragma unroll
        for (int j = 0; j < 16; j++) {
            float t2 = 0.f;
#pragma unroll
            for (int w2 = 0; w2 < 8; w2++) t2 += red[16 + w2 * 16 + j];
            float s = t2 / Z;
            v[j] = s; sq += s * s;
        }
        float coef = (sq / (1.f + sq)) * rsqrtf(sq);
#pragma unroll
        for (int j = 0; j < 16; j++) v[j] *= coef;
        __syncthreads();

        if (t == 0) {
            for (int i = tid; i < 1152; i += 256) {
                const float4* Pd = (const float4*)(P + i * 16);
                float4 p0 = Pd[0], p1 = Pd[1], p2 = Pd[2], p3 = Pd[3];
                float dot = p0.x*v[0]+p0.y*v[1]+p0.z*v[2]+p0.w*v[3]
                          + p1.x*v[4]+p1.y*v[5]+p1.z*v[6]+p1.w*v[7]
                          + p2.x*v[8]+p2.y*v[9]+p2.z*v[10]+p2.w*v[11]
                          + p3.x*v[12]+p3.y*v[13]+p3.z*v[14]+p3.w*v[15];
                logits[i] += dot;
            }
            __syncthreads();
        }
    }

    if (tid < 16) g_vecs[(b * 10 + o) * 16 + tid] = v[tid];
}

// ======================================================================
// class norms -> softmax -> d_out[0..2560); argmax one-hot mask -> g_dec
// ======================================================================
__global__ void mask_kernel(float* __restrict__ cls_out)
{
    int b = blockIdx.x;
    int lane = threadIdx.x;
    float nrm = -1e30f;
    if (lane < 10) {
        float sq = 0.f;
        const float* vp = g_vecs + (b * 10 + lane) * 16;
#pragma unroll
        for (int j = 0; j < 16; j++) { float t = vp[j]; sq += t * t; }
        nrm = sqrtf(sq);
    }
    float m = nrm;
#pragma unroll
    for (int off = 16; off; off >>= 1) m = fmaxf(m, __shfl_xor_sync(0xffffffffu, m, off));
    float e = (lane < 10) ? expf(nrm - m) : 0.f;
    float Z = e;
#pragma unroll
    for (int off = 16; off; off >>= 1) Z += __shfl_xor_sync(0xffffffffu, Z, off);
    if (lane < 10) cls_out[b * 10 + lane] = e / Z;

    float bv = nrm; int bi = (lane < 10) ? lane : 1000;
#pragma unroll
    for (int off = 16; off; off >>= 1) {
        float ov = __shfl_xor_sync(0xffffffffu, bv, off);
        int   oi = __shfl_xor_sync(0xffffffffu, bi, off);
        if (ov > bv || (ov == bv && oi < bi)) { bv = ov; bi = oi; }
    }
#pragma unroll
    for (int r2 = 0; r2 < 5; r2++) {
        int k = lane + 32 * r2;
        int oo = k >> 4, j = k & 15;
        g_dec[b * 160 + k] = (oo == bi) ? g_vecs[(b * 10 + oo) * 16 + j] : 0.f;
    }
}

// ======================================================================
// generic SGEMM C = act(A[M,K] @ B[K,N] + bias), 64x64 tile (unchanged)
// ======================================================================
template<int ACT>
__global__ __launch_bounds__(256) void gemm_bias_act(
    const float* __restrict__ A, const float* __restrict__ Bm,
    const float* __restrict__ bias, float* __restrict__ C,
    int M, int N, int K)
{
    __shared__ __align__(16) float As[16][64];
    __shared__ __align__(16) float Bs[16][64];
    int tid = threadIdx.x;
    int bn = blockIdx.x * 64, bm = blockIdx.y * 64;
    int tx = tid & 15, ty = tid >> 4;
    int ar = tid >> 2, ac = (tid & 3) * 4;
    int br = tid >> 4, bc = (tid & 15) * 4;

    unsigned long long acc2[4][2];
#pragma unroll
    for (int i = 0; i < 4; i++) { acc2[i][0] = 0ull; acc2[i][1] = 0ull; }

    for (int k0 = 0; k0 < K; k0 += 16) {
        float4 av = *(const float4*)(A + (size_t)(bm + ar) * K + k0 + ac);
        As[ac + 0][ar] = av.x; As[ac + 1][ar] = av.y;
        As[ac + 2][ar] = av.z; As[ac + 3][ar] = av.w;
        float4 bvv;
        int bcol = bn + bc;
        if (bcol + 3 < N) {
            bvv = *(const float4*)(Bm + (size_t)(k0 + br) * N + bcol);
        } else {
            bvv.x = (bcol + 0 < N) ? Bm[(size_t)(k0 + br) * N + bcol + 0] : 0.f;
            bvv.y = (bcol + 1 < N) ? Bm[(size_t)(k0 + br) * N + bcol + 1] : 0.f;
            bvv.z = (bcol + 2 < N) ? Bm[(size_t)(k0 + br) * N + bcol + 2] : 0.f;
            bvv.w = (bcol + 3 < N) ? Bm[(size_t)(k0 + br) * N + bcol + 3] : 0.f;
        }
        *(float4*)(&Bs[br][bc]) = bvv;
        __syncthreads();
#pragma unroll
        for (int kk = 0; kk < 16; kk++) {
            float4 a = *(const float4*)(&As[kk][ty * 4]);
            ulonglong2 bq = *(const ulonglong2*)(&Bs[kk][tx * 4]);
            unsigned long long a2[4] = { pack2(a.x), pack2(a.y), pack2(a.z), pack2(a.w) };
#pragma unroll
            for (int i = 0; i < 4; i++) {
                fma2(acc2[i][0], a2[i], bq.x);
                fma2(acc2[i][1], a2[i], bq.y);
            }
        }
        __syncthreads();
    }
#pragma unroll
    for (int i = 0; i < 4; i++) {
        int mrow = bm + ty * 4 + i;
        float2 a0 = unpack2(acc2[i][0]);
        float2 a1 = unpack2(acc2[i][1]);
        float vals[4] = { a0.x, a0.y, a1.x, a1.y };
#pragma unroll
        for (int j = 0; j < 4; j++) {
            int ncol = bn + tx * 4 + j;
            if (ncol < N) {
                float vv = vals[j] + bias[ncol];
                if (ACT == 0) vv = vv > 0.f ? vv : 0.f;
                else          vv = 1.f / (1.f + expf(-vv));
                C[(size_t)mrow * N + ncol] = vv;
            }
        }
    }
}

// ======================================================================
extern "C" void kernel_launch(void* const* d_in, const int* in_sizes, int n_in,
                              void* d_out, int out_size)
{
    const float* x   = (const float*)d_in[0];
    const float* c1w = (const float*)d_in[1];
    const float* c1b = (const float*)d_in[2];
    const float* pw  = (const float*)d_in[3];
    const float* pb  = (const float*)d_in[4];
    const float* rw  = (const float*)d_in[5];
    const float* w1  = (const float*)d_in[6];
    const float* b1  = (const float*)d_in[7];
    const float* w2  = (const float*)d_in[8];
    const float* b2  = (const float*)d_in[9];
    const float* w3  = (const float*)d_in[10];
    const float* b3  = (const float*)d_in[11];
    float* out = (float*)d_out;

    cudaFuncSetAttribute(routing_kernel, cudaFuncAttributeMaxDynamicSharedMemorySize,
                         ROUTE_SMEM_FLOATS * 4);
    cudaFuncSetAttribute(prim_mma_kernel, cudaFuncAttributeMaxDynamicSharedMemorySize,
                         PRIM_SMEM);

    conv1_kernel<<<dim3(256, 8), 320>>>(x, c1w, c1b);
    wsplit_kernel<<<(81 * 256 * 256 + 255) / 256, 256>>>(pw);
    hsplit_kernel<<<dim3(13, 8, 256), dim3(32, 8)>>>();
    prim_mma_kernel<<<dim3(72, 2), 512, PRIM_SMEM>>>(pb);   // profiled slot
    squash_kernel<<<(256 * 1152 + 255) / 256, 256>>>();
    routing_kernel<<<dim3(10, 256), 256, ROUTE_SMEM_FLOATS * 4>>>(rw);
    mask_kernel<<<256, 32>>>(out);
    gemm_bias_act<0><<<dim3(8, 4), 256>>>(g_dec, w1, b1, g_h1, 256, 512, 160);
    gemm_bias_act<0><<<dim3(16, 4), 256>>>(g_h1, w2, b2, g_h2, 256, 1024, 512);
    gemm_bias_act<1><<<dim3(13, 4), 256>>>(g_h2, w3, b3, out + 2560, 256, 784, 1024);
}

// round 17
// speedup vs baseline: 1.7188x; 1.0728x over previous
#include <cuda_runtime.h>
#include <cuda_bf16.h>
#include <stdint.h>
#include <math.h>

// ---------------- problem constants ----------------
#define BSZ     256
#define NCLS    10
#define INCAPS  1152

// ---------------- scratch (device globals; no allocs allowed) ----------------
__device__ __nv_bfloat16 g_hh [256 * 400 * 256];  // h hi, NHWC: [(b*400+p)*256+ic]
__device__ __nv_bfloat16 g_hl [256 * 400 * 256];  // h lo
__device__ __nv_bfloat16 g_wh2[81 * 256 * 256];   // w hi: [(tap*256+oc)*256+ic]
__device__ __nv_bfloat16 g_wl2[81 * 256 * 256];   // w lo
__device__ float g_p   [256 * 256 * 36];    // prim conv output
__device__ float g_u   [256 * 1152 * 8];    // squashed primary capsules
__device__ float g_vecs[256 * 10 * 16];     // routed output vectors
__device__ float g_dec [256 * 160];         // masked decoder input
__device__ float g_h1  [256 * 512];
__device__ float g_h2  [256 * 1024];

// ---------------- packed f32x2 helpers (Blackwell FFMA2) ----------------
__device__ __forceinline__ unsigned long long pack2(float v) {
    unsigned long long r;
    asm("mov.b64 %0, {%1, %1};" : "=l"(r) : "f"(v));
    return r;
}
__device__ __forceinline__ void fma2(unsigned long long& d,
                                     unsigned long long a, unsigned long long b) {
    asm("fma.rn.f32x2 %0, %1, %2, %0;" : "+l"(d) : "l"(a), "l"(b));
}
__device__ __forceinline__ float2 unpack2(unsigned long long v) {
    float2 r;
    asm("mov.b64 {%0, %1}, %2;" : "=f"(r.x), "=f"(r.y) : "l"(v));
    return r;
}

// ---------------- cp.async helpers ----------------
__device__ __forceinline__ void cp_async16(unsigned int smem_addr, const void* gptr) {
    asm volatile("cp.async.cg.shared.global [%0], [%1], 16;"
                 :: "r"(smem_addr), "l"(gptr));
}
__device__ __forceinline__ void cp_commit() {
    asm volatile("cp.async.commit_group;");
}
template<int N>
__device__ __forceinline__ void cp_wait() {
    asm volatile("cp.async.wait_group %0;" :: "n"(N));
}

// ---------------- warp MMA helpers (base PTX, works on sm_103 non-'a') ----
__device__ __forceinline__ void ldsm_x4(unsigned& r0, unsigned& r1,
                                        unsigned& r2, unsigned& r3, unsigned addr) {
    asm volatile("ldmatrix.sync.aligned.m8n8.x4.shared.b16 {%0,%1,%2,%3}, [%4];"
                 : "=r"(r0), "=r"(r1), "=r"(r2), "=r"(r3) : "r"(addr));
}
__device__ __forceinline__ void mma16816(float* c, const unsigned* a, const unsigned* b) {
    asm volatile(
        "mma.sync.aligned.m16n8k16.row.col.f32.bf16.bf16.f32 "
        "{%0,%1,%2,%3}, {%4,%5,%6,%7}, {%8,%9}, {%0,%1,%2,%3};"
        : "+f"(c[0]), "+f"(c[1]), "+f"(c[2]), "+f"(c[3])
        : "r"(a[0]), "r"(a[1]), "r"(a[2]), "r"(a[3]), "r"(b[0]), "r"(b[1]));
}

// ======================================================================
// conv1 + relu, fused with hi/lo bf16 split and NHWC transpose:
// writes g_hh/g_hl [(b*400+p)*256+ic] directly (no fp32 intermediate).
// ======================================================================
__global__ __launch_bounds__(320) void conv1_kernel(
    const float* __restrict__ x, const float* __restrict__ w,
    const float* __restrict__ bias)
{
    __shared__ __align__(16) float img[784];
    __shared__ __align__(16) float ws[81 * 32];
    int b = blockIdx.x, oc0 = blockIdx.y * 32;
    int tid = threadIdx.x;

    for (int idx = tid; idx < 784; idx += 320) img[idx] = x[b * 784 + idx];
    for (int idx = tid; idx < 32 * 81; idx += 320) {
        int oc = idx / 81, tap = idx - oc * 81;
        ws[tap * 32 + oc] = w[(oc0 + oc) * 81 + tap];
    }
    __syncthreads();

    int ocg = tid & 7;
    int pg  = tid >> 3;
    int row = pg >> 1;
    int c0  = (pg & 1) * 10;

    unsigned long long acc2[10][2];
#pragma unroll
    for (int p = 0; p < 10; p++) { acc2[p][0] = 0ull; acc2[p][1] = 0ull; }

#pragma unroll 1
    for (int ky = 0; ky < 9; ky++) {
        const float* r = img + (row + ky) * 28 + c0;
        unsigned long long xv2[18];
#pragma unroll
        for (int j = 0; j < 18; j++) xv2[j] = pack2(r[j]);
#pragma unroll
        for (int kx = 0; kx < 9; kx++) {
            ulonglong2 wv = *(const ulonglong2*)(ws + (ky * 9 + kx) * 32 + ocg * 4);
#pragma unroll
            for (int p = 0; p < 10; p++) {
                fma2(acc2[p][0], xv2[p + kx], wv.x);
                fma2(acc2[p][1], xv2[p + kx], wv.y);
            }
        }
    }
    int ocb = oc0 + ocg * 4;
    float bv[4] = { bias[ocb], bias[ocb + 1], bias[ocb + 2], bias[ocb + 3] };
#pragma unroll
    for (int p = 0; p < 10; p++) {
        float2 a0 = unpack2(acc2[p][0]);
        float2 a1 = unpack2(acc2[p][1]);
        float vals[4] = { a0.x + bv[0], a0.y + bv[1], a1.x + bv[2], a1.y + bv[3] };
        size_t o = ((size_t)b * 400 + row * 20 + c0 + p) * 256 + ocb;
        __nv_bfloat16 hh[4], hl[4];
#pragma unroll
        for (int c = 0; c < 4; c++) {
            float v = vals[c] > 0.f ? vals[c] : 0.f;
            __nv_bfloat16 hi = __float2bfloat16(v);
            hh[c] = hi;
            hl[c] = __float2bfloat16(v - __bfloat162float(hi));
        }
        *(ulonglong1*)(g_hh + o) = *(ulonglong1*)hh;   // 8B store
        *(ulonglong1*)(g_hl + o) = *(ulonglong1*)hl;
    }
}

// ======================================================================
// wsplit: pw[oc][ic][tap] -> g_wh2/g_wl2 [(tap*256+oc)*256+ic] (bf16 hi/lo)
// ======================================================================
__global__ void wsplit_kernel(const float* __restrict__ w)
{
    int idx = blockIdx.x * 256 + threadIdx.x;
    if (idx >= 81 * 256 * 256) return;
    int ic  = idx & 255;
    int r   = idx >> 8;
    int oc  = r & 255;
    int tap = r >> 8;
    float v = w[(oc * 256 + ic) * 81 + tap];
    __nv_bfloat16 hi = __float2bfloat16(v);
    g_wh2[idx] = hi;
    g_wl2[idx] = __float2bfloat16(v - __bfloat162float(hi));
}

// dummy no-op: keeps prim in the ncu capture slot
__global__ void dummy_kernel() {}

// ======================================================================
// prim conv as warp-MMA bf16 implicit GEMM (tap-decomposed, 2-term split)
// C[pos 128][oc 128] per block; 16 warps (4x4), warp tile 32(pos) x 32(oc).
// THREE-STAGE cp.async pipeline: ONE barrier per iteration, 2 iterations of
// fill slack. Fragments loaded once per k-step; 3 MMA passes from registers.
// grid 72x2 = 144 blocks = one wave. smem 192KB.
// ======================================================================
#define TILE_B   16384                // one 128x64 bf16 tile
#define BUF_B    (4 * TILE_B)         // Ah, Al, Bh, Bl
#define STAGES   3
#define PRIM_SMEM (STAGES * BUF_B)    // 192 KB

__global__ __launch_bounds__(512, 1) void prim_mma_kernel(const float* __restrict__ bias)
{
    extern __shared__ __align__(128) char smem[];
    unsigned sbase = (unsigned)__cvta_generic_to_shared(smem);
    int tid = threadIdx.x, warp = tid >> 5, lane = tid & 31;
    int mpos0 = blockIdx.x * 128;
    int oc0 = blockIdx.y * 128;

    int wm = (warp >> 2) * 32;          // warp pos offset within tile
    int wn = (warp & 3) * 32;           // warp oc offset within tile

    // ---- fill indexing: 512 threads; each fills 2 of 8 j-chunks of one row x 4 arrays
    int frow = tid & 127, fq = tid >> 7;   // fq 0..3
    int pg = mpos0 + frow;
    int fb = pg / 36, fr = pg - fb * 36;
    int foy = fr / 6, fox = fr - foy * 6;
    size_t abase = ((size_t)fb * 400 + foy * 40 + fox * 2) * 256;  // + (ky*20+kx)*256 + ic0
    size_t wbase = (size_t)(oc0 + frow) * 256;                     // + tap*65536 + ic0
    unsigned drow = frow * 128;
    int swz = frow & 7;

    float acc[2][4][4];
#pragma unroll
    for (int mi = 0; mi < 2; mi++)
#pragma unroll
        for (int ni = 0; ni < 4; ni++)
#pragma unroll
            for (int k = 0; k < 4; k++) acc[mi][ni][k] = 0.f;

    // fill helper target iteration -> buffer
    auto fill_iter = [&](int it, unsigned dst) {
        int tap = it >> 2, ck = it & 3;
        int ky = tap / 9, kx = tap - ky * 9;
        const __nv_bfloat16* sAh = g_hh + abase + (ky * 20 + kx) * 256 + ck * 64;
        const __nv_bfloat16* sAl = g_hl + abase + (ky * 20 + kx) * 256 + ck * 64;
        const __nv_bfloat16* sBh = g_wh2 + wbase + (size_t)tap * 65536 + ck * 64;
        const __nv_bfloat16* sBl = g_wl2 + wbase + (size_t)tap * 65536 + ck * 64;
#pragma unroll
        for (int j0 = 0; j0 < 2; j0++) {
            int j = fq * 2 + j0;
            unsigned so = drow + (unsigned)((j ^ swz) * 16);
            cp_async16(dst + so,              sAh + j * 8);
            cp_async16(dst + TILE_B + so,     sAl + j * 8);
            cp_async16(dst + 2 * TILE_B + so, sBh + j * 8);
            cp_async16(dst + 3 * TILE_B + so, sBl + j * 8);
        }
        cp_commit();
    };

    // ---- prologue: prefetch iterations 0 and 1
    fill_iter(0, sbase);
    fill_iter(1, sbase + BUF_B);

#pragma unroll 1
    for (int it = 0; it < 324; it++) {
        // wait fill(it) complete (<=1 outstanding group: fill(it+1))
        cp_wait<1>();
        __syncthreads();   // all warps past compute(it-1); buf[(it+2)%3] reusable; buf[it%3] visible

        if (it + 2 < 324)
            fill_iter(it + 2, sbase + ((it + 2) % STAGES) * BUF_B);

        unsigned bufb = sbase + (it % STAGES) * BUF_B;
#pragma unroll
        for (int ks = 0; ks < 4; ks++) {
            unsigned ah[2][4], al[2][4], bh[4][2], bl[4][2];
#pragma unroll
            for (int mi = 0; mi < 2; mi++) {
                int row = wm + mi * 16 + (lane & 15);
                int chunk = ks * 2 + (lane >> 4);
                unsigned addr = bufb + row * 128 + ((chunk ^ (row & 7)) * 16);
                ldsm_x4(ah[mi][0], ah[mi][1], ah[mi][2], ah[mi][3], addr);
                ldsm_x4(al[mi][0], al[mi][1], al[mi][2], al[mi][3], addr + TILE_B);
            }
#pragma unroll
            for (int nj = 0; nj < 2; nj++) {
                int row = wn + nj * 16 + ((lane >> 4) << 3) + (lane & 7);
                int chunk = ks * 2 + ((lane >> 3) & 1);
                unsigned addr = bufb + 2 * TILE_B + row * 128 + ((chunk ^ (row & 7)) * 16);
                ldsm_x4(bh[nj * 2][0], bh[nj * 2][1],
                        bh[nj * 2 + 1][0], bh[nj * 2 + 1][1], addr);
                ldsm_x4(bl[nj * 2][0], bl[nj * 2][1],
                        bl[nj * 2 + 1][0], bl[nj * 2 + 1][1], addr + TILE_B);
            }
#pragma unroll
            for (int mi = 0; mi < 2; mi++)
#pragma unroll
                for (int ni = 0; ni < 4; ni++) {
                    mma16816(acc[mi][ni], ah[mi], bh[ni]);
                    mma16816(acc[mi][ni], al[mi], bh[ni]);
                    mma16816(acc[mi][ni], ah[mi], bl[ni]);
                }
        }
    }

    // ---- epilogue: acc -> g_p with bias
    int g = lane >> 2, tg = lane & 3;
#pragma unroll
    for (int mi = 0; mi < 2; mi++) {
        int pos0 = mpos0 + wm + mi * 16 + g;
        int pos1 = pos0 + 8;
        int b0 = pos0 / 36, pp0 = pos0 - b0 * 36;
        int b1 = pos1 / 36, pp1 = pos1 - b1 * 36;
#pragma unroll
        for (int ni = 0; ni < 4; ni++) {
            int oc = oc0 + wn + ni * 8 + tg * 2;
            float bv0 = bias[oc], bv1 = bias[oc + 1];
            g_p[((size_t)b0 * 256 + oc)     * 36 + pp0] = acc[mi][ni][0] + bv0;
            g_p[((size_t)b0 * 256 + oc + 1) * 36 + pp0] = acc[mi][ni][1] + bv1;
            g_p[((size_t)b1 * 256 + oc)     * 36 + pp1] = acc[mi][ni][2] + bv0;
            g_p[((size_t)b1 * 256 + oc + 1) * 36 + pp1] = acc[mi][ni][3] + bv1;
        }
    }
}

// ======================================================================
// primary capsule squash (unchanged)
// ======================================================================
__global__ void squash_kernel()
{
    int idx = blockIdx.x * 256 + threadIdx.x;
    if (idx >= 256 * 1152) return;
    int b = idx / 1152;
    int i = idx - b * 1152;
    int m = i / 36;
    int s = i - m * 36;
    const float* src = g_p + (b * 256 + m) * 36 + s;
    float v[8]; float sq = 0.f;
#pragma unroll
    for (int d = 0; d < 8; d++) { float t = src[d * 1152]; v[d] = t; sq += t * t; }
    float coef = (sq / (1.f + sq)) * rsqrtf(sq);
    float* dst = g_u + (size_t)idx * 8;
#pragma unroll
    for (int d = 0; d < 8; d++) dst[d] = v[d] * coef;
}

// ======================================================================
// fused routing-by-agreement (unchanged)
// ======================================================================
__device__ __forceinline__ float warpSum(float v) {
#pragma unroll
    for (int o = 16; o; o >>= 1) v += __shfl_xor_sync(0xffffffffu, v, o);
    return v;
}
__device__ __forceinline__ float warpMax(float v) {
#pragma unroll
    for (int o = 16; o; o >>= 1) v = fmaxf(v, __shfl_xor_sync(0xffffffffu, v, o));
    return v;
}

#define ROUTE_SMEM_FLOATS (18432 + 1152 + 160)

__global__ __launch_bounds__(256) void routing_kernel(const float* __restrict__ rw)
{
    extern __shared__ float sm[];
    float* P      = sm;
    float* logits = sm + 18432;
    float* red    = sm + 19584;

    int o = blockIdx.x, b = blockIdx.y;
    int tid = threadIdx.x;
    int lane = tid & 31, wid = tid >> 5;

    float sacc[16];
#pragma unroll
    for (int j = 0; j < 16; j++) sacc[j] = 0.f;

    for (int i = tid; i < 1152; i += 256) {
        const float4* up = (const float4*)(g_u + ((size_t)b * 1152 + i) * 8);
        float4 ua = up[0], ub = up[1];
        float uu[8] = { ua.x, ua.y, ua.z, ua.w, ub.x, ub.y, ub.z, ub.w };
        const float4* wr = (const float4*)(rw + (size_t)(o * 1152 + i) * 128);
        float pj[16];
#pragma unroll
        for (int j = 0; j < 16; j++) pj[j] = 0.f;
#pragma unroll
        for (int d = 0; d < 8; d++) {
            float ud = uu[d];
            float4 w0 = wr[d*4+0], w1 = wr[d*4+1], w2 = wr[d*4+2], w3 = wr[d*4+3];
            pj[0]+=ud*w0.x; pj[1]+=ud*w0.y; pj[2]+=ud*w0.z; pj[3]+=ud*w0.w;
            pj[4]+=ud*w1.x; pj[5]+=ud*w1.y; pj[6]+=ud*w1.z; pj[7]+=ud*w1.w;
            pj[8]+=ud*w2.x; pj[9]+=ud*w2.y; pj[10]+=ud*w2.z; pj[11]+=ud*w2.w;
            pj[12]+=ud*w3.x; pj[13]+=ud*w3.y; pj[14]+=ud*w3.z; pj[15]+=ud*w3.w;
        }
        float4* Pd = (float4*)(P + i * 16);
        Pd[0] = make_float4(pj[0], pj[1], pj[2], pj[3]);
        Pd[1] = make_float4(pj[4], pj[5], pj[6], pj[7]);
        Pd[2] = make_float4(pj[8], pj[9], pj[10], pj[11]);
        Pd[3] = make_float4(pj[12], pj[13], pj[14], pj[15]);
#pragma unroll
        for (int j = 0; j < 16; j++) sacc[j] += pj[j];
    }

    __syncthreads();
#pragma unroll
    for (int j = 0; j < 16; j++) sacc[j] = warpSum(sacc[j]);
    if (lane == 0) {
#pragma unroll
        for (int j = 0; j < 16; j++) red[16 + wid * 16 + j] = sacc[j];
    }
    __syncthreads();
    if (tid < 16) {
        float t = 0.f;
#pragma unroll
        for (int w2 = 0; w2 < 8; w2++) t += red[16 + w2 * 16 + tid];
        red[144 + tid] = t;
    }
    __syncthreads();

    float v[16];
    {
        float sq = 0.f;
#pragma unroll
        for (int j = 0; j < 16; j++) { float s = red[144 + j] * (1.f / 1152.f); v[j] = s; sq += s * s; }
        float coef = (sq / (1.f + sq)) * rsqrtf(sq);
#pragma unroll
        for (int j = 0; j < 16; j++) v[j] *= coef;
    }
    __syncthreads();

    for (int i = tid; i < 1152; i += 256) {
        const float4* Pd = (const float4*)(P + i * 16);
        float4 p0 = Pd[0], p1 = Pd[1], p2 = Pd[2], p3 = Pd[3];
        logits[i] = p0.x*v[0]+p0.y*v[1]+p0.z*v[2]+p0.w*v[3]
                  + p1.x*v[4]+p1.y*v[5]+p1.z*v[6]+p1.w*v[7]
                  + p2.x*v[8]+p2.y*v[9]+p2.z*v[10]+p2.w*v[11]
                  + p3.x*v[12]+p3.y*v[13]+p3.z*v[14]+p3.w*v[15];
    }
    __syncthreads();

    for (int t = 0; t < 2; t++) {
        float lm = -1e30f;
        for (int i = tid; i < 1152; i += 256) lm = fmaxf(lm, logits[i]);
        lm = warpMax(lm);
        if (lane == 0) red[wid] = lm;
        __syncthreads();
        float M = red[0];
#pragma unroll
        for (int w2 = 1; w2 < 8; w2++) M = fmaxf(M, red[w2]);
        __syncthreads();

        float zp = 0.f;
        float sp[16];
#pragma unroll
        for (int j = 0; j < 16; j++) sp[j] = 0.f;
        for (int i = tid; i < 1152; i += 256) {
            float e = expf(logits[i] - M);
            zp += e;
            const float4* Pd = (const float4*)(P + i * 16);
            float4 p0 = Pd[0], p1 = Pd[1], p2 = Pd[2], p3 = Pd[3];
            sp[0]+=e*p0.x; sp[1]+=e*p0.y; sp[2]+=e*p0.z; sp[3]+=e*p0.w;
            sp[4]+=e*p1.x; sp[5]+=e*p1.y; sp[6]+=e*p1.z; sp[7]+=e*p1.w;
            sp[8]+=e*p2.x; sp[9]+=e*p2.y; sp[10]+=e*p2.z; sp[11]+=e*p2.w;
            sp[12]+=e*p3.x; sp[13]+=e*p3.y; sp[14]+=e*p3.z; sp[15]+=e*p3.w;
        }
        zp = warpSum(zp);
#pragma unroll
        for (int j = 0; j < 16; j++) sp[j] = warpSum(sp[j]);
        if (lane == 0) {
            red[wid] = zp;
#pragma unroll
            for (int j = 0; j < 16; j++) red[16 + wid * 16 + j] = sp[j];
        }
        __syncthreads();
        float Z = 0.f;
#pragma unroll
        for (int w2 = 0; w2 < 8; w2++) Z += red[w2];
        float sq = 0.f;
#pragma unroll
        for (int j = 0; j < 16; j++) {
            float t2 = 0.f;
#pragma unroll
            for (int w2 = 0; w2 < 8; w2++) t2 += red[16 + w2 * 16 + j];
            float s = t2 / Z;
            v[j] = s; sq += s * s;
        }
        float coef = (sq / (1.f + sq)) * rsqrtf(sq);
#pragma unroll
        for (int j = 0; j < 16; j++) v[j] *= coef;
        __syncthreads();

        if (t == 0) {
            for (int i = tid; i < 1152; i += 256) {
                const float4* Pd = (const float4*)(P + i * 16);
                float4 p0 = Pd[0], p1 = Pd[1], p2 = Pd[2], p3 = Pd[3];
                float dot = p0.x*v[0]+p0.y*v[1]+p0.z*v[2]+p0.w*v[3]
                          + p1.x*v[4]+p1.y*v[5]+p1.z*v[6]+p1.w*v[7]
                          + p2.x*v[8]+p2.y*v[9]+p2.z*v[10]+p2.w*v[11]
                          + p3.x*v[12]+p3.y*v[13]+p3.z*v[14]+p3.w*v[15];
                logits[i] += dot;
            }
            __syncthreads();
        }
    }

    if (tid < 16) g_vecs[(b * 10 + o) * 16 + tid] = v[tid];
}

// ======================================================================
// class norms -> softmax -> d_out[0..2560); argmax one-hot mask -> g_dec
// ======================================================================
__global__ void mask_kernel(float* __restrict__ cls_out)
{
    int b = blockIdx.x;
    int lane = threadIdx.x;
    float nrm = -1e30f;
    if (lane < 10) {
        float sq = 0.f;
        const float* vp = g_vecs + (b * 10 + lane) * 16;
#pragma unroll
        for (int j = 0; j < 16; j++) { float t = vp[j]; sq += t * t; }
        nrm = sqrtf(sq);
    }
    float m = nrm;
#pragma unroll
    for (int off = 16; off; off >>= 1) m = fmaxf(m, __shfl_xor_sync(0xffffffffu, m, off));
    float e = (lane < 10) ? expf(nrm - m) : 0.f;
    float Z = e;
#pragma unroll
    for (int off = 16; off; off >>= 1) Z += __shfl_xor_sync(0xffffffffu, Z, off);
    if (lane < 10) cls_out[b * 10 + lane] = e / Z;

    float bv = nrm; int bi = (lane < 10) ? lane : 1000;
#pragma unroll
    for (int off = 16; off; off >>= 1) {
        float ov = __shfl_xor_sync(0xffffffffu, bv, off);
        int   oi = __shfl_xor_sync(0xffffffffu, bi, off);
        if (ov > bv || (ov == bv && oi < bi)) { bv = ov; bi = oi; }
    }
#pragma unroll
    for (int r2 = 0; r2 < 5; r2++) {
        int k = lane + 32 * r2;
        int oo = k >> 4, j = k & 15;
        g_dec[b * 160 + k] = (oo == bi) ? g_vecs[(b * 10 + oo) * 16 + j] : 0.f;
    }
}

// ======================================================================
// generic SGEMM C = act(A[M,K] @ B[K,N] + bias), 64x64 tile (unchanged)
// ======================================================================
template<int ACT>
__global__ __launch_bounds__(256) void gemm_bias_act(
    const float* __restrict__ A, const float* __restrict__ Bm,
    const float* __restrict__ bias, float* __restrict__ C,
    int M, int N, int K)
{
    __shared__ __align__(16) float As[16][64];
    __shared__ __align__(16) float Bs[16][64];
    int tid = threadIdx.x;
    int bn = blockIdx.x * 64, bm = blockIdx.y * 64;
    int tx = tid & 15, ty = tid >> 4;
    int ar = tid >> 2, ac = (tid & 3) * 4;
    int br = tid >> 4, bc = (tid & 15) * 4;

    unsigned long long acc2[4][2];
#pragma unroll
    for (int i = 0; i < 4; i++) { acc2[i][0] = 0ull; acc2[i][1] = 0ull; }

    for (int k0 = 0; k0 < K; k0 += 16) {
        float4 av = *(const float4*)(A + (size_t)(bm + ar) * K + k0 + ac);
        As[ac + 0][ar] = av.x; As[ac + 1][ar] = av.y;
        As[ac + 2][ar] = av.z; As[ac + 3][ar] = av.w;
        float4 bvv;
        int bcol = bn + bc;
        if (bcol + 3 < N) {
            bvv = *(const float4*)(Bm + (size_t)(k0 + br) * N + bcol);
        } else {
            bvv.x = (bcol + 0 < N) ? Bm[(size_t)(k0 + br) * N + bcol + 0] : 0.f;
            bvv.y = (bcol + 1 < N) ? Bm[(size_t)(k0 + br) * N + bcol + 1] : 0.f;
            bvv.z = (bcol + 2 < N) ? Bm[(size_t)(k0 + br) * N + bcol + 2] : 0.f;
            bvv.w = (bcol + 3 < N) ? Bm[(size_t)(k0 + br) * N + bcol + 3] : 0.f;
        }
        *(float4*)(&Bs[br][bc]) = bvv;
        __syncthreads();
#pragma unroll
        for (int kk = 0; kk < 16; kk++) {
            float4 a = *(const float4*)(&As[kk][ty * 4]);
            ulonglong2 bq = *(const ulonglong2*)(&Bs[kk][tx * 4]);
            unsigned long long a2[4] = { pack2(a.x), pack2(a.y), pack2(a.z), pack2(a.w) };
#pragma unroll
            for (int i = 0; i < 4; i++) {
                fma2(acc2[i][0], a2[i], bq.x);
                fma2(acc2[i][1], a2[i], bq.y);
            }
        }
        __syncthreads();
    }
#pragma unroll
    for (int i = 0; i < 4; i++) {
        int mrow = bm + ty * 4 + i;
        float2 a0 = unpack2(acc2[i][0]);
        float2 a1 = unpack2(acc2[i][1]);
        float vals[4] = { a0.x, a0.y, a1.x, a1.y };
#pragma unroll
        for (int j = 0; j < 4; j++) {
            int ncol = bn + tx * 4 + j;
            if (ncol < N) {
                float vv = vals[j] + bias[ncol];
                if (ACT == 0) vv = vv > 0.f ? vv : 0.f;
                else          vv = 1.f / (1.f + expf(-vv));
                C[(size_t)mrow * N + ncol] = vv;
            }
        }
    }
}

// ======================================================================
extern "C" void kernel_launch(void* const* d_in, const int* in_sizes, int n_in,
                              void* d_out, int out_size)
{
    const float* x   = (const float*)d_in[0];
    const float* c1w = (const float*)d_in[1];
    const float* c1b = (const float*)d_in[2];
    const float* pw  = (const float*)d_in[3];
    const float* pb  = (const float*)d_in[4];
    const float* rw  = (const float*)d_in[5];
    const float* w1  = (const float*)d_in[6];
    const float* b1  = (const float*)d_in[7];
    const float* w2  = (const float*)d_in[8];
    const float* b2  = (const float*)d_in[9];
    const float* w3  = (const float*)d_in[10];
    const float* b3  = (const float*)d_in[11];
    float* out = (float*)d_out;

    cudaFuncSetAttribute(routing_kernel, cudaFuncAttributeMaxDynamicSharedMemorySize,
                         ROUTE_SMEM_FLOATS * 4);
    cudaFuncSetAttribute(prim_mma_kernel, cudaFuncAttributeMaxDynamicSharedMemorySize,
                         PRIM_SMEM);

    conv1_kernel<<<dim3(256, 8), 320>>>(x, c1w, c1b);   // writes g_hh/g_hl directly
    wsplit_kernel<<<(81 * 256 * 256 + 255) / 256, 256>>>(pw);
    dummy_kernel<<<1, 32>>>();                           // keeps prim in ncu slot
    prim_mma_kernel<<<dim3(72, 2), 512, PRIM_SMEM>>>(pb);
    squash_kernel<<<(256 * 1152 + 255) / 256, 256>>>();
    routing_kernel<<<dim3(10, 256), 256, ROUTE_SMEM_FLOATS * 4>>>(rw);
    mask_kernel<<<256, 32>>>(out);
    gemm_bias_act<0><<<dim3(8, 4), 256>>>(g_dec, w1, b1, g_h1, 256, 512, 160);
    gemm_bias_act<0><<<dim3(16, 4), 256>>>(g_h1, w2, b2, g_h2, 256, 1024, 512);
    gemm_bias_act<1><<<dim3(13, 4), 256>>>(g_h2, w3, b3, out + 2560, 256, 784, 1024);
}